// round 14
// baseline (speedup 1.0000x reference)
#include <cuda_runtime.h>
#include <cuda_bf16.h>
#include <math.h>
#include <stdint.h>

#define BB 4
#define NN 2048
#define KK 30
#define HH 128
#define NNODES (BB*NN)
#define NTILES (NNODES/4)
#define SP 136          // padded bf16 row stride for 128-col MMA activation buffers

// ---------------- device scratch ----------------
__device__ __align__(16) float g_hV  [NNODES*HH];
__device__ __align__(16) float g_Apre[NNODES*HH];
__device__ __align__(16) float g_Cpre[NNODES*HH];
__device__ __align__(16) float g_Q   [NNODES*9];
__device__ __align__(16) float g_hV1 [NNODES*HH];
__device__ __align__(16) float g_Wef [16*HH];
__device__ __align__(16) float g_bef [HH];
// pre-split FF weights: [kp][n] bf16x2 packs, kp = k0>>1
__device__ __align__(16) uint32_t g_WiH[64*512],  g_WiL[64*512];
__device__ __align__(16) uint32_t g_WoH[256*128], g_WoL[256*128];

// ---------------- geometry helpers ----------------
struct F3{float x,y,z;};
__device__ __forceinline__ F3 f3(float a,float b,float c){F3 r;r.x=a;r.y=b;r.z=c;return r;}
__device__ __forceinline__ F3 sub3(F3 a,F3 b){return f3(a.x-b.x,a.y-b.y,a.z-b.z);}
__device__ __forceinline__ float dot3(F3 a,F3 b){return a.x*b.x+a.y*b.y+a.z*b.z;}
__device__ __forceinline__ F3 cross3(F3 a,F3 b){
  return f3(a.y*b.z-a.z*b.y, a.z*b.x-a.x*b.z, a.x*b.y-a.y*b.x);
}
__device__ __forceinline__ F3 norm3(F3 v){
  float n=dot3(v,v);
  if(n>0.f){float r=rsqrtf(n);return f3(v.x*r,v.y*r,v.z*r);}
  return f3(0.f,0.f,0.f);
}
__device__ __forceinline__ float sgnf(float x){return (x>0.f)?1.f:((x<0.f)?-1.f:0.f);}
__device__ __forceinline__ float gelu(float x){return 0.5f*x*(1.f+erff(x*0.7071067811865475f));}
__device__ __forceinline__ float clip1(float x){return fminf(fmaxf(x,-1.f+1e-7f),1.f-1e-7f);}
__device__ __forceinline__ F3 loadXf(const float* X,int b,int f){
  const float* p=X+(((b*NN)+(f/3))*4+(f%3))*3;
  return f3(p[0],p[1],p[2]);
}

// ---------------- mma helpers ----------------
__device__ __forceinline__ uint32_t smem_u32(const void* p){
  uint32_t a;
  asm("{ .reg .u64 t; cvta.to.shared.u64 t, %1; cvt.u32.u64 %0, t; }":"=r"(a):"l"(p));
  return a;
}
__device__ __forceinline__ uint32_t pkbf(float a,float b){
  __nv_bfloat162 v=__halves2bfloat162(__float2bfloat16(a),__float2bfloat16(b));
  return *reinterpret_cast<uint32_t*>(&v);
}
__device__ __forceinline__ void split2(float a,float b,uint32_t&hi,uint32_t&lo){
  __nv_bfloat16 ha=__float2bfloat16(a), hb=__float2bfloat16(b);
  __nv_bfloat162 hv=__halves2bfloat162(ha,hb);
  hi=*reinterpret_cast<uint32_t*>(&hv);
  lo=pkbf(a-__bfloat162float(ha), b-__bfloat162float(hb));
}

#define LDM4(r,addr) \
  asm volatile("ldmatrix.sync.aligned.m8n8.x4.shared.b16 {%0,%1,%2,%3},[%4];" \
    : "=r"((r)[0]),"=r"((r)[1]),"=r"((r)[2]),"=r"((r)[3]) : "r"(addr))

#define MMA4(c,a,b0,b1) \
  asm volatile("mma.sync.aligned.m16n8k16.row.col.f32.bf16.bf16.f32 " \
    "{%0,%1,%2,%3},{%4,%5,%6,%7},{%8,%9},{%0,%1,%2,%3};" \
    : "+f"((c)[0]),"+f"((c)[1]),"+f"((c)[2]),"+f"((c)[3]) \
    : "r"((a)[0]),"r"((a)[1]),"r"((a)[2]),"r"((a)[3]),"r"(b0),"r"(b1))

// ---------------- kernel 0a: fold We through W1's hE block ----------------
__global__ void k_fold(const float* __restrict__ Wew,const float* __restrict__ Web,
                       const float* __restrict__ W1w,const float* __restrict__ W1b){
  int j=threadIdx.x; int kb=blockIdx.x;
  if(kb<16){
    float s=0.f;
    for(int m=0;m<128;m++) s+=Wew[kb*128+m]*W1w[(128+m)*128+j];
    g_Wef[kb*128+j]=s;
  }else{
    float s=W1b[j];
    for(int m=0;m<128;m++) s+=Web[m]*W1w[(128+m)*128+j];
    g_bef[j]=s;
  }
}

// ---------------- kernel 0b: pre-split FF weights [kp][n] ----------------
__global__ void k_prep_ff(const float* __restrict__ Wiw,const float* __restrict__ Wow){
  int idx=blockIdx.x*256+threadIdx.x;
  if(idx<32768){
    int kp=idx>>9, n=idx&511;
    split2(Wiw[(size_t)(2*kp)*512+n],Wiw[(size_t)(2*kp+1)*512+n],g_WiH[idx],g_WiL[idx]);
  }else{
    int i=idx-32768; int kp=i>>7, n=i&127;
    split2(Wow[(size_t)(2*kp)*128+n],Wow[(size_t)(2*kp+1)*128+n],g_WoH[i],g_WoL[i]);
  }
}

// ---------------- kernel 1: node geometry + hV + HMMA Apre/Cpre ----------------
__global__ __launch_bounds__(256) void k_node(
    const float* __restrict__ X,const float* __restrict__ Wvw,
    const float* __restrict__ Wvb,const float* __restrict__ W1w){
  __shared__ float sfeat[32][21];
  __shared__ float sQ[32][9];
  __shared__ float shv[32][128];
  __shared__ __align__(16) char shvhi[32*SP*2];
  __shared__ __align__(16) char shvlo[32*SP*2];
  int t=threadIdx.x, w=t>>5, lane=t&31;
  int base=blockIdx.x*32;

  if(t<96){
    int nl=t/3, c=t-nl*3; int g=base+nl; int b=g>>11, n=g&(NN-1);
    int tt=3*n+c-1;
    float cD=1.f,sD=0.f,cA=1.f,sA=0.f;
    if(tt>=0 && tt<=3*NN-4){
      F3 x0=loadXf(X,b,tt),x1=loadXf(X,b,tt+1),x2=loadXf(X,b,tt+2),x3=loadXf(X,b,tt+3);
      F3 u0=norm3(sub3(x1,x0)),u1=norm3(sub3(x2,x1)),u2=norm3(sub3(x3,x2));
      F3 n0=norm3(cross3(u0,u1)),n1=norm3(cross3(u1,u2));
      float cd=clip1(dot3(n0,n1));
      F3 v=norm3(cross3(n0,n1));
      float sg=sgnf(-dot3(v,u1));
      cD=(sg==0.f)?1.f:cd;
      sD=sg*sqrtf(fmaxf(0.f,1.f-cd*cd));
      float ca=clip1(dot3(u0,u1));
      cA=ca; sA=sqrtf(fmaxf(0.f,1.f-ca*ca));
    }
    sfeat[nl][c]=cD; sfeat[nl][3+c]=sD; sfeat[nl][6+c]=cA; sfeat[nl][9+c]=sA;
  }else if(t<128){
    int nl=t-96; int g=base+nl; int b=g>>11, n=g&(NN-1);
    float Qr[9];
    if(n==NN-1){
      #pragma unroll
      for(int k2=0;k2<9;k2++)Qr[k2]=0.f;
    }else{
      F3 x0=loadXf(X,b,3*n),x1=loadXf(X,b,3*n+1),x2=loadXf(X,b,3*n+2);
      F3 u0=norm3(sub3(x1,x0)),u1=norm3(sub3(x2,x1));
      F3 n0=norm3(cross3(u0,u1)),b1=norm3(sub3(u0,u1));
      F3 r2=cross3(b1,n0);
      Qr[0]=b1.x;Qr[1]=b1.y;Qr[2]=b1.z;
      Qr[3]=n0.x;Qr[4]=n0.y;Qr[5]=n0.z;
      Qr[6]=r2.x;Qr[7]=r2.y;Qr[8]=r2.z;
    }
    #pragma unroll
    for(int k2=0;k2<9;k2++){sQ[nl][k2]=Qr[k2];g_Q[g*9+k2]=Qr[k2];}
  }
  __syncthreads();
  if(t<96){
    int nl=t/3, a=t-nl*3; int g=base+nl; int b=g>>11, n=g&(NN-1);
    int atom=(a==0)?0:(a+1);
    const float* Xp=X+((b*NN+n)*4)*3;
    F3 d=f3(Xp[atom*3]-Xp[0],Xp[atom*3+1]-Xp[1],Xp[atom*3+2]-Xp[2]);
    F3 du=f3(sQ[nl][0]*d.x+sQ[nl][1]*d.y+sQ[nl][2]*d.z,
             sQ[nl][3]*d.x+sQ[nl][4]*d.y+sQ[nl][5]*d.z,
             sQ[nl][6]*d.x+sQ[nl][7]*d.y+sQ[nl][8]*d.z);
    du=norm3(du);
    sfeat[nl][12+a*3+0]=du.x; sfeat[nl][12+a*3+1]=du.y; sfeat[nl][12+a*3+2]=du.z;
  }
  __syncthreads();
  {
    int j=t&127, half=t>>7;
    float wv[21];
    #pragma unroll
    for(int i=0;i<21;i++) wv[i]=Wvw[i*128+j];
    float bv=Wvb[j];
    for(int r=0;r<16;r++){
      int nl=half*16+r;
      float a=bv;
      #pragma unroll
      for(int i=0;i<21;i++) a+=sfeat[nl][i]*wv[i];
      shv[nl][j]=a;
      g_hV[(size_t)(base+nl)*128+j]=a;
    }
  }
  __syncthreads();
  for(int idx=t; idx<2048; idx+=256){
    int row=idx>>6, cp=idx&63;
    float a=shv[row][cp*2], bq=shv[row][cp*2+1];
    uint32_t hi,lo; split2(a,bq,hi,lo);
    *(uint32_t*)(shvhi+(size_t)(row*SP+cp*2)*2)=hi;
    *(uint32_t*)(shvlo+(size_t)(row*SP+cp*2)*2)=lo;
  }
  __syncthreads();
  {
    uint32_t hibase=smem_u32(shvhi), lobase=smem_u32(shvlo);
    uint32_t a_off=(uint32_t)(((lane&15)*SP+((lane>>4)<<3))*2);
    bool isA=(w<4);
    #pragma unroll
    for(int nt2=0;nt2<4;nt2++){
      int n0=w*32+nt2*8;
      int col=n0+(lane>>2);
      int ccol=isA?col:(col-128);
      int rbase=isA?0:256;
      uint32_t fhi[8][2], flo[8][2];
      #pragma unroll
      for(int ks=0;ks<8;ks++)
        #pragma unroll
        for(int p=0;p<2;p++){
          int k0=ks*16+(lane&3)*2+p*8;
          float wa=W1w[(size_t)(rbase+k0)*128+ccol];
          float wb=W1w[(size_t)(rbase+k0+1)*128+ccol];
          split2(wa,wb,fhi[ks][p],flo[ks][p]);
        }
      #pragma unroll
      for(int Mt=0;Mt<2;Mt++){
        float c[4]={0,0,0,0};
        uint32_t abase=a_off+(uint32_t)(Mt*16*SP*2);
        #pragma unroll
        for(int ks=0;ks<8;ks++){
          uint32_t ah[4],al[4];
          LDM4(ah, hibase+abase+ks*32);
          LDM4(al, lobase+abase+ks*32);
          MMA4(c,ah,fhi[ks][0],fhi[ks][1]);
          MMA4(c,ah,flo[ks][0],flo[ks][1]);
          MMA4(c,al,fhi[ks][0],fhi[ks][1]);
        }
        int m0=Mt*16+(lane>>2), m1=m0+8;
        int cc0=(isA?n0:(n0-128))+(lane&3)*2;
        float* dst=isA?g_Apre:g_Cpre;
        float2 p0; p0.x=c[0]; p0.y=c[1];
        float2 p1; p1.x=c[2]; p1.y=c[3];
        *(float2*)&dst[(size_t)(base+m0)*128+cc0]=p0;
        *(float2*)&dst[(size_t)(base+m1)*128+cc0]=p1;
      }
    }
  }
}

// ---------------- kernel 2: full-HMMA edge MLP + msg + LN1 ----------------
#define OFF_H1HI  0
#define OFF_H1LO  34816
#define OFF_E16HI 69632
#define OFF_E16LO 75776
#define OFF_APB   81920
#define OFF_NBR   83968
#define OFF_SG2   84480
#define OFF_SY    86528
#define OFF_SPART 88640
#define EDGE_SMEM_BYTES 92736

__global__ __launch_bounds__(256,2) void k_edge(
    const float* __restrict__ X,const int* __restrict__ Eidx,
    const float* __restrict__ W2w,const float* __restrict__ W2b,
    const float* __restrict__ W3w,const float* __restrict__ W3b,
    const float* __restrict__ l1g,const float* __restrict__ l1b){
  extern __shared__ __align__(16) char smc[];
  uint32_t sbase=smem_u32(smc);
  float* sApb=(float*)(smc+OFF_APB);
  int*   snbr=(int*)(smc+OFF_NBR);
  float* sg2 =(float*)(smc+OFF_SG2);
  float* sy  =(float*)(smc+OFF_SY);
  float* spart=(float*)(smc+OFF_SPART);
  int t=threadIdx.x, w=t>>5, lane=t&31;
  int wbase=w*16;

  uint32_t w2hi[2][8][2], w2lo[2][8][2];
  {
    int n=wbase+(lane>>2);
    #pragma unroll
    for(int nt=0;nt<2;nt++)
      #pragma unroll
      for(int ks=0;ks<8;ks++)
        #pragma unroll
        for(int p=0;p<2;p++){
          int k0=ks*16+(lane&3)*2+p*8;
          float wa=W2w[k0*128+n+nt*8], wb=W2w[(k0+1)*128+n+nt*8];
          split2(wa,wb,w2hi[nt][ks][p],w2lo[nt][ks][p]);
        }
  }
  float b2v[2][2];
  #pragma unroll
  for(int nt=0;nt<2;nt++){
    b2v[nt][0]=W2b[wbase+nt*8+(lane&3)*2];
    b2v[nt][1]=W2b[wbase+nt*8+(lane&3)*2+1];
  }

  for(int tile=blockIdx.x; tile<NTILES; tile+=gridDim.x){
    int node_base=tile*4;
    int b=node_base>>11;

    // ---- phase 1: edge geometry -> e16 bf16 hi/lo ; Apre staging ----
    if(t<128){
      int nl=t>>5, slot=t&31; int g=node_base+nl; int n=g&(NN-1);
      int nbr=(slot<KK)?Eidx[g*KK+slot]:0;
      snbr[t]=nbr;
      char* ehi=smc+OFF_E16HI+(size_t)t*48;
      char* elo=smc+OFF_E16LO+(size_t)t*48;
      if(slot<KK){
        float out[16];
        const float* Qo=g_Q+g*9;
        F3 q0=f3(Qo[0],Qo[1],Qo[2]),q1=f3(Qo[3],Qo[4],Qo[5]),q2=f3(Qo[6],Qo[7],Qo[8]);
        const float* Xo=X+(size_t)(b*NN+n)*12;
        F3 xa=f3(Xo[0],Xo[1],Xo[2]);
        const float* Xn=X+(size_t)(b*NN+nbr)*12;
        const int ord[4]={1,0,2,3};
        #pragma unroll
        for(int a=0;a<4;a++){
          int atom=ord[a];
          F3 p=f3(Xn[atom*3],Xn[atom*3+1],Xn[atom*3+2]);
          F3 d=sub3(p,xa);
          F3 du=norm3(f3(dot3(q0,d),dot3(q1,d),dot3(q2,d)));
          out[a*3]=du.x; out[a*3+1]=du.y; out[a*3+2]=du.z;
        }
        const float* Qn=g_Q+(size_t)(b*NN+nbr)*9;
        float R00=q0.x*Qn[0]+q1.x*Qn[3]+q2.x*Qn[6];
        float R01=q0.x*Qn[1]+q1.x*Qn[4]+q2.x*Qn[7];
        float R02=q0.x*Qn[2]+q1.x*Qn[5]+q2.x*Qn[8];
        float R10=q0.y*Qn[0]+q1.y*Qn[3]+q2.y*Qn[6];
        float R11=q0.y*Qn[1]+q1.y*Qn[4]+q2.y*Qn[7];
        float R12=q0.y*Qn[2]+q1.y*Qn[5]+q2.y*Qn[8];
        float R20=q0.z*Qn[0]+q1.z*Qn[3]+q2.z*Qn[6];
        float R21=q0.z*Qn[1]+q1.z*Qn[4]+q2.z*Qn[7];
        float R22=q0.z*Qn[2]+q1.z*Qn[5]+q2.z*Qn[8];
        float m0=0.5f*sqrtf(fabsf(1.f+R00-R11-R22));
        float m1=0.5f*sqrtf(fabsf(1.f-R00+R11-R22));
        float m2=0.5f*sqrtf(fabsf(1.f-R00-R11+R22));
        float qx=sgnf(R21-R12)*m0;
        float qy=sgnf(R02-R20)*m1;
        float qz=sgnf(R10-R01)*m2;
        float qw=0.5f*sqrtf(fmaxf(0.f,1.f+R00+R11+R22));
        float nq=qx*qx+qy*qy+qz*qz+qw*qw;
        if(nq>0.f){float r=rsqrtf(nq);qx*=r;qy*=r;qz*=r;qw*=r;}
        else{qx=0.f;qy=0.f;qz=0.f;qw=0.f;}
        out[12]=qx;out[13]=qy;out[14]=qz;out[15]=qw;
        uint4 h0,l0,h1,l1;
        split2(out[0],out[1],h0.x,l0.x);  split2(out[2],out[3],h0.y,l0.y);
        split2(out[4],out[5],h0.z,l0.z);  split2(out[6],out[7],h0.w,l0.w);
        split2(out[8],out[9],h1.x,l1.x);  split2(out[10],out[11],h1.y,l1.y);
        split2(out[12],out[13],h1.z,l1.z);split2(out[14],out[15],h1.w,l1.w);
        *(uint4*)(ehi)=h0;    *(uint4*)(ehi+16)=h1;
        *(uint4*)(elo)=l0;    *(uint4*)(elo+16)=l1;
      }else{
        uint4 z=make_uint4(0,0,0,0);
        *(uint4*)(ehi)=z; *(uint4*)(ehi+16)=z;
        *(uint4*)(elo)=z; *(uint4*)(elo+16)=z;
      }
    }
    {
      int i0=t, i1=t+256;
      sApb[i0]=g_Apre[(size_t)node_base*128+i0]+g_bef[i0&127];
      sApb[i1]=g_Apre[(size_t)node_base*128+i1]+g_bef[i1&127];
    }
    __syncthreads();

    // ---- phase 2: layer-1 MMA (K=16) + Apre/Cpre/gelu -> h1 hi/lo ----
    {
      uint32_t wefhi[2][2], weflo[2][2];
      {
        int n=wbase+(lane>>2);
        #pragma unroll
        for(int nt=0;nt<2;nt++)
          #pragma unroll
          for(int p=0;p<2;p++){
            int k0=(lane&3)*2+p*8;
            float wa=g_Wef[k0*128+n+nt*8], wb=g_Wef[(k0+1)*128+n+nt*8];
            split2(wa,wb,wefhi[nt][p],weflo[nt][p]);
          }
      }
      uint32_t a_off16=(uint32_t)((lane&15)*48+(lane>>4)*16);
      for(int Mt=0;Mt<8;Mt++){
        float c[2][4]={{0,0,0,0},{0,0,0,0}};
        uint32_t ah[4],al[4];
        LDM4(ah, sbase+OFF_E16HI+a_off16+(uint32_t)(Mt*16*48));
        LDM4(al, sbase+OFF_E16LO+a_off16+(uint32_t)(Mt*16*48));
        #pragma unroll
        for(int nt=0;nt<2;nt++){
          MMA4(c[nt],ah,wefhi[nt][0],wefhi[nt][1]);
          MMA4(c[nt],ah,weflo[nt][0],weflo[nt][1]);
          MMA4(c[nt],al,wefhi[nt][0],wefhi[nt][1]);
        }
        int m0=Mt*16+(lane>>2), m1=m0+8;
        int node=Mt>>1;
        bool k0=(m0&31)<KK, k1=(m1&31)<KK;
        const float* cp0p=g_Cpre+(size_t)(b*NN+snbr[m0])*128;
        const float* cp1p=g_Cpre+(size_t)(b*NN+snbr[m1])*128;
        #pragma unroll
        for(int nt=0;nt<2;nt++){
          int n0=wbase+nt*8+(lane&3)*2;
          float2 ap=*(const float2*)&sApb[node*128+n0];
          float2 cp0=*(const float2*)&cp0p[n0];
          float2 cp1=*(const float2*)&cp1p[n0];
          float v0=k0?gelu(c[nt][0]+ap.x+cp0.x):0.f;
          float v1=k0?gelu(c[nt][1]+ap.y+cp0.y):0.f;
          float v2=k1?gelu(c[nt][2]+ap.x+cp1.x):0.f;
          float v3=k1?gelu(c[nt][3]+ap.y+cp1.y):0.f;
          uint32_t hi,lo;
          split2(v0,v1,hi,lo);
          *(uint32_t*)(smc+OFF_H1HI+(size_t)(m0*SP+n0)*2)=hi;
          *(uint32_t*)(smc+OFF_H1LO+(size_t)(m0*SP+n0)*2)=lo;
          split2(v2,v3,hi,lo);
          *(uint32_t*)(smc+OFF_H1HI+(size_t)(m1*SP+n0)*2)=hi;
          *(uint32_t*)(smc+OFF_H1LO+(size_t)(m1*SP+n0)*2)=lo;
        }
      }
    }
    __syncthreads();

    // ---- phase 3: layer-2 MMA + in-register node reduction -> sg2 ----
    {
      float acc[4][2][2];
      #pragma unroll
      for(int nd=0;nd<4;nd++)
        #pragma unroll
        for(int nt=0;nt<2;nt++){acc[nd][nt][0]=0.f;acc[nd][nt][1]=0.f;}
      uint32_t a_off=(uint32_t)(((lane&15)*SP+((lane>>4)<<3))*2);
      for(int Mt=0;Mt<8;Mt++){
        float c[2][4]={{0,0,0,0},{0,0,0,0}};
        uint32_t abase=a_off+(uint32_t)(Mt*16*SP*2);
        #pragma unroll
        for(int ks=0;ks<8;ks++){
          uint32_t ah[4],al[4];
          LDM4(ah, sbase+OFF_H1HI+abase+ks*32);
          LDM4(al, sbase+OFF_H1LO+abase+ks*32);
          #pragma unroll
          for(int nt=0;nt<2;nt++){
            MMA4(c[nt],ah,w2hi[nt][ks][0],w2hi[nt][ks][1]);
            MMA4(c[nt],ah,w2lo[nt][ks][0],w2lo[nt][ks][1]);
            MMA4(c[nt],al,w2hi[nt][ks][0],w2hi[nt][ks][1]);
          }
        }
        int m0=Mt*16+(lane>>2), m1=m0+8;
        int node=Mt>>1;
        bool k0=(m0&31)<KK, k1=(m1&31)<KK;
        #pragma unroll
        for(int nt=0;nt<2;nt++){
          float v0=k0?gelu(c[nt][0]+b2v[nt][0]):0.f;
          float v1=k0?gelu(c[nt][1]+b2v[nt][1]):0.f;
          float v2=k1?gelu(c[nt][2]+b2v[nt][0]):0.f;
          float v3=k1?gelu(c[nt][3]+b2v[nt][1]):0.f;
          acc[node][nt][0]+=v0+v2;
          acc[node][nt][1]+=v1+v3;
        }
      }
      #pragma unroll
      for(int nd=0;nd<4;nd++)
        #pragma unroll
        for(int nt=0;nt<2;nt++)
          #pragma unroll
          for(int cp=0;cp<2;cp++){
            float v=acc[nd][nt][cp];
            v+=__shfl_xor_sync(0xffffffffu,v,4);
            v+=__shfl_xor_sync(0xffffffffu,v,8);
            v+=__shfl_xor_sync(0xffffffffu,v,16);
            acc[nd][nt][cp]=v;
          }
      if(lane<4){
        #pragma unroll
        for(int nd=0;nd<4;nd++)
          #pragma unroll
          for(int nt=0;nt<2;nt++){
            sg2[nd*128+wbase+nt*8+lane*2  ]=acc[nd][nt][0];
            sg2[nd*128+wbase+nt*8+lane*2+1]=acc[nd][nt][1];
          }
      }
    }
    __syncthreads();

    // ---- phase 4: msg = g2@W3, K-split across 2 halves ----
    {
      int j=t&127, kh=t>>7;
      const float* wp=W3w+(size_t)(kh*64)*128+j;
      float a0=0.f,a1=0.f,a2=0.f,a3=0.f;
      int ib=kh*64;
      #pragma unroll 4
      for(int i=0;i<64;i++){
        float wv=wp[(size_t)i*128];
        int ii=ib+i;
        a0+=sg2[0*128+ii]*wv; a1+=sg2[1*128+ii]*wv;
        a2+=sg2[2*128+ii]*wv; a3+=sg2[3*128+ii]*wv;
      }
      float* sp=spart+kh*512;
      sp[0*128+j]=a0; sp[1*128+j]=a1; sp[2*128+j]=a2; sp[3*128+j]=a3;
    }
    __syncthreads();
    {
      #pragma unroll
      for(int o=0;o<2;o++){
        int oo=t+o*256; int nd=oo>>7, j=oo&127;
        float m=(spart[nd*128+j]+spart[512+nd*128+j])*(1.f/(float)KK)+W3b[j];
        sy[nd*132+j]=g_hV[(size_t)(node_base+nd)*128+j]+m;
      }
    }
    __syncthreads();

    // ---- phase 5: LN1 (warp per node) -> g_hV1 ----
    if(w<4){
      float4 v=*(const float4*)&sy[w*132+lane*4];
      float s=v.x+v.y+v.z+v.w;
      #pragma unroll
      for(int o=16;o;o>>=1) s+=__shfl_xor_sync(0xffffffffu,s,o);
      float m=s*(1.f/128.f);
      float dx=v.x-m,dy=v.y-m,dz=v.z-m,dw=v.w-m;
      float q=dx*dx+dy*dy+dz*dz+dw*dw;
      #pragma unroll
      for(int o=16;o;o>>=1) q+=__shfl_xor_sync(0xffffffffu,q,o);
      float rs=rsqrtf(q*(1.f/128.f)+1e-5f);
      float4 gg=*(const float4*)&l1g[lane*4];
      float4 bb=*(const float4*)&l1b[lane*4];
      float4 o4;
      o4.x=dx*rs*gg.x+bb.x; o4.y=dy*rs*gg.y+bb.y;
      o4.z=dz*rs*gg.z+bb.z; o4.w=dw*rs*gg.w+bb.w;
      *(float4*)&g_hV1[(size_t)(node_base+w)*128+lane*4]=o4;
    }
    __syncthreads();
  }
}

// ---------------- kernel 3: HMMA FF + LN2, M=32/block, 2 CTA/SM ----------------
#define FF2_AHI 0
#define FF2_ALO 8704
#define FF2_HHI 17408
#define FF2_HLO 26112
#define FF2_Y   34816
#define FF2_SMEM 51712

__global__ __launch_bounds__(256,2) void k_ff2(
    const float* __restrict__ bi,const float* __restrict__ bo,
    const float* __restrict__ l2g,const float* __restrict__ l2b,
    float* __restrict__ out){
  extern __shared__ __align__(16) char smc[];
  uint32_t sbase=smem_u32(smc);
  float* sy=(float*)(smc+FF2_Y);
  int t=threadIdx.x, w=t>>5, lane=t&31;
  int base=blockIdx.x*32;

  for(int idx=t; idx<2048; idx+=256){
    int row=idx>>6, cp=idx&63;
    float2 v=*(const float2*)&g_hV1[(size_t)(base+row)*128+cp*2];
    uint32_t hi,lo; split2(v.x,v.y,hi,lo);
    *(uint32_t*)(smc+FF2_AHI+(size_t)(row*SP+cp*2)*2)=hi;
    *(uint32_t*)(smc+FF2_ALO+(size_t)(row*SP+cp*2)*2)=lo;
  }
  __syncthreads();

  float C[2][2][4];
  #pragma unroll
  for(int Mt=0;Mt<2;Mt++)
    #pragma unroll
    for(int nt=0;nt<2;nt++)
      #pragma unroll
      for(int q=0;q<4;q++) C[Mt][nt][q]=0.f;

  uint32_t a_off=(uint32_t)(((lane&15)*SP+((lane>>4)<<3))*2);

  for(int ch=0;ch<4;ch++){
    // ---- GEMM1: pre-split fragment loads, shared A ----
    {
      uint32_t fhi[2][8][2], flo[2][8][2];
      #pragma unroll
      for(int nt=0;nt<2;nt++){
        int n=ch*128+w*16+nt*8+(lane>>2);
        #pragma unroll
        for(int ks=0;ks<8;ks++)
          #pragma unroll
          for(int p=0;p<2;p++){
            int kp=ks*8+(lane&3)+p*4;
            fhi[nt][ks][p]=g_WiH[kp*512+n];
            flo[nt][ks][p]=g_WiL[kp*512+n];
          }
      }
      float bi0[2],bi1[2];
      #pragma unroll
      for(int nt=0;nt<2;nt++){
        bi0[nt]=bi[ch*128+w*16+nt*8+(lane&3)*2];
        bi1[nt]=bi[ch*128+w*16+nt*8+(lane&3)*2+1];
      }
      #pragma unroll
      for(int Mt=0;Mt<2;Mt++){
        float c[2][4]={{0,0,0,0},{0,0,0,0}};
        uint32_t abase=a_off+(uint32_t)(Mt*16*SP*2);
        #pragma unroll
        for(int ks=0;ks<8;ks++){
          uint32_t ah[4],al[4];
          LDM4(ah, sbase+FF2_AHI+abase+ks*32);
          LDM4(al, sbase+FF2_ALO+abase+ks*32);
          #pragma unroll
          for(int nt=0;nt<2;nt++){
            MMA4(c[nt],ah,fhi[nt][ks][0],fhi[nt][ks][1]);
            MMA4(c[nt],ah,flo[nt][ks][0],flo[nt][ks][1]);
            MMA4(c[nt],al,fhi[nt][ks][0],fhi[nt][ks][1]);
          }
        }
        int m0=Mt*16+(lane>>2), m1=m0+8;
        #pragma unroll
        for(int nt=0;nt<2;nt++){
          int n0=w*16+nt*8+(lane&3)*2;
          uint32_t hi,lo;
          split2(gelu(c[nt][0]+bi0[nt]),gelu(c[nt][1]+bi1[nt]),hi,lo);
          *(uint32_t*)(smc+FF2_HHI+(size_t)(m0*SP+n0)*2)=hi;
          *(uint32_t*)(smc+FF2_HLO+(size_t)(m0*SP+n0)*2)=lo;
          split2(gelu(c[nt][2]+bi0[nt]),gelu(c[nt][3]+bi1[nt]),hi,lo);
          *(uint32_t*)(smc+FF2_HHI+(size_t)(m1*SP+n0)*2)=hi;
          *(uint32_t*)(smc+FF2_HLO+(size_t)(m1*SP+n0)*2)=lo;
        }
      }
    }
    __syncthreads();

    // ---- GEMM2: pre-split fragment loads, shared A ----
    {
      uint32_t fhi[2][8][2], flo[2][8][2];
      #pragma unroll
      for(int nt=0;nt<2;nt++){
        int n=w*16+nt*8+(lane>>2);
        #pragma unroll
        for(int ks=0;ks<8;ks++)
          #pragma unroll
          for(int p=0;p<2;p++){
            int kp=ch*64+ks*8+(lane&3)+p*4;
            fhi[nt][ks][p]=g_WoH[kp*128+n];
            flo[nt][ks][p]=g_WoL[kp*128+n];
          }
      }
      #pragma unroll
      for(int Mt=0;Mt<2;Mt++){
        uint32_t abase=a_off+(uint32_t)(Mt*16*SP*2);
        #pragma unroll
        for(int ks=0;ks<8;ks++){
          uint32_t ah[4],al[4];
          LDM4(ah, sbase+FF2_HHI+abase+ks*32);
          LDM4(al, sbase+FF2_HLO+abase+ks*32);
          #pragma unroll
          for(int nt=0;nt<2;nt++){
            MMA4(C[Mt][nt],ah,fhi[nt][ks][0],fhi[nt][ks][1]);
            MMA4(C[Mt][nt],ah,flo[nt][ks][0],flo[nt][ks][1]);
            MMA4(C[Mt][nt],al,fhi[nt][ks][0],fhi[nt][ks][1]);
          }
        }
      }
    }
    __syncthreads();
  }

  {
    #pragma unroll
    for(int Mt=0;Mt<2;Mt++){
      int m0=Mt*16+(lane>>2), m1=m0+8;
      #pragma unroll
      for(int nt=0;nt<2;nt++){
        int n0=w*16+nt*8+(lane&3)*2;
        float b0=bo[n0], b1=bo[n0+1];
        sy[m0*132+n0  ]=C[Mt][nt][0]+b0+g_hV1[(size_t)(base+m0)*128+n0];
        sy[m0*132+n0+1]=C[Mt][nt][1]+b1+g_hV1[(size_t)(base+m0)*128+n0+1];
        sy[m1*132+n0  ]=C[Mt][nt][2]+b0+g_hV1[(size_t)(base+m1)*128+n0];
        sy[m1*132+n0+1]=C[Mt][nt][3]+b1+g_hV1[(size_t)(base+m1)*128+n0+1];
      }
    }
  }
  __syncthreads();
  for(int r=0;r<4;r++){
    int row=w*4+r;
    float4 v=*(const float4*)&sy[row*132+lane*4];
    float s=v.x+v.y+v.z+v.w;
    #pragma unroll
    for(int o=16;o;o>>=1) s+=__shfl_xor_sync(0xffffffffu,s,o);
    float m=s*(1.f/128.f);
    float dx=v.x-m,dy=v.y-m,dz=v.z-m,dw=v.w-m;
    float q=dx*dx+dy*dy+dz*dz+dw*dw;
    #pragma unroll
    for(int o=16;o;o>>=1) q+=__shfl_xor_sync(0xffffffffu,q,o);
    float rs=rsqrtf(q*(1.f/128.f)+1e-5f);
    float4 gg=*(const float4*)&l2g[lane*4];
    float4 bb=*(const float4*)&l2b[lane*4];
    float4 o4;
    o4.x=dx*rs*gg.x+bb.x; o4.y=dy*rs*gg.y+bb.y;
    o4.z=dz*rs*gg.z+bb.z; o4.w=dw*rs*gg.w+bb.w;
    *(float4*)&out[(size_t)(base+row)*128+lane*4]=o4;
  }
}

// ---------------- launch ----------------
extern "C" void kernel_launch(void* const* d_in, const int* in_sizes, int n_in,
                              void* d_out, int out_size){
  const float* X  =(const float*)d_in[0];
  const int*  Eidx=(const int*  )d_in[1];
  const float* Wvw=(const float*)d_in[2];
  const float* Wvb=(const float*)d_in[3];
  const float* Wew=(const float*)d_in[4];
  const float* Web=(const float*)d_in[5];
  const float* W1w=(const float*)d_in[6];
  const float* W1b=(const float*)d_in[7];
  const float* W2w=(const float*)d_in[8];
  const float* W2b=(const float*)d_in[9];
  const float* W3w=(const float*)d_in[10];
  const float* W3b=(const float*)d_in[11];
  const float* Wiw=(const float*)d_in[12];
  const float* Wib=(const float*)d_in[13];
  const float* Wow=(const float*)d_in[14];
  const float* Wob=(const float*)d_in[15];
  const float* l1g=(const float*)d_in[16];
  const float* l1b=(const float*)d_in[17];
  const float* l2g=(const float*)d_in[18];
  const float* l2b=(const float*)d_in[19];
  float* out=(float*)d_out;

  cudaFuncSetAttribute(k_edge, cudaFuncAttributeMaxDynamicSharedMemorySize,
                       EDGE_SMEM_BYTES);
  cudaFuncSetAttribute(k_ff2, cudaFuncAttributeMaxDynamicSharedMemorySize,
                       FF2_SMEM);

  k_fold<<<17,128>>>(Wew,Web,W1w,W1b);
  k_prep_ff<<<256,256>>>(Wiw,Wow);
  k_node<<<NNODES/32,256>>>(X,Wvw,Wvb,W1w);
  k_edge<<<296,256,EDGE_SMEM_BYTES>>>(X,Eidx,W2w,W2b,W3w,W3b,l1g,l1b);
  k_ff2<<<NNODES/32,256,FF2_SMEM>>>(Wib,Wob,l2g,l2b,out);
}

// round 15
// speedup vs baseline: 1.0257x; 1.0257x over previous
#include <cuda_runtime.h>
#include <cuda_bf16.h>
#include <math.h>
#include <stdint.h>

#define BB 4
#define NN 2048
#define KK 30
#define HH 128
#define NNODES (BB*NN)
#define NTILES (NNODES/4)
#define SP 136          // padded bf16 row stride for 128-col MMA activation buffers

// ---------------- device scratch ----------------
__device__ __align__(16) float g_hV  [NNODES*HH];
__device__ __align__(16) float g_Apre[NNODES*HH];
__device__ __align__(16) float g_Cpre[NNODES*HH];
__device__ __align__(16) float g_Q   [NNODES*9];
__device__ __align__(16) float g_hV1 [NNODES*HH];
__device__ __align__(16) float g_Wef [16*HH];
__device__ __align__(16) float g_bef [HH];

// ---------------- geometry helpers ----------------
struct F3{float x,y,z;};
__device__ __forceinline__ F3 f3(float a,float b,float c){F3 r;r.x=a;r.y=b;r.z=c;return r;}
__device__ __forceinline__ F3 sub3(F3 a,F3 b){return f3(a.x-b.x,a.y-b.y,a.z-b.z);}
__device__ __forceinline__ float dot3(F3 a,F3 b){return a.x*b.x+a.y*b.y+a.z*b.z;}
__device__ __forceinline__ F3 cross3(F3 a,F3 b){
  return f3(a.y*b.z-a.z*b.y, a.z*b.x-a.x*b.z, a.x*b.y-a.y*b.x);
}
__device__ __forceinline__ F3 norm3(F3 v){
  float n=dot3(v,v);
  if(n>0.f){float r=rsqrtf(n);return f3(v.x*r,v.y*r,v.z*r);}
  return f3(0.f,0.f,0.f);
}
__device__ __forceinline__ float sgnf(float x){return (x>0.f)?1.f:((x<0.f)?-1.f:0.f);}
__device__ __forceinline__ float gelu(float x){return 0.5f*x*(1.f+erff(x*0.7071067811865475f));}
__device__ __forceinline__ float clip1(float x){return fminf(fmaxf(x,-1.f+1e-7f),1.f-1e-7f);}
__device__ __forceinline__ F3 loadXf(const float* X,int b,int f){
  const float* p=X+(((b*NN)+(f/3))*4+(f%3))*3;
  return f3(p[0],p[1],p[2]);
}

// ---------------- mma helpers ----------------
__device__ __forceinline__ uint32_t smem_u32(const void* p){
  uint32_t a;
  asm("{ .reg .u64 t; cvta.to.shared.u64 t, %1; cvt.u32.u64 %0, t; }":"=r"(a):"l"(p));
  return a;
}
// single-instruction packed f32x2 -> bf16x2 (low = a, high = b), rn rounding
__device__ __forceinline__ uint32_t pkbf(float a,float b){
  uint32_t r;
  asm("cvt.rn.bf16x2.f32 %0, %1, %2;" : "=r"(r) : "f"(b), "f"(a));
  return r;
}
// 6-instruction hi/lo split: hi = pack(bf(a),bf(b)); lo = pack(a-hi.a, b-hi.b)
__device__ __forceinline__ void split2(float a,float b,uint32_t&hi,uint32_t&lo){
  uint32_t h=pkbf(a,b);
  float ha=__uint_as_float(h<<16);
  float hb=__uint_as_float(h&0xffff0000u);
  lo=pkbf(a-ha,b-hb);
  hi=h;
}

#define LDM4(r,addr) \
  asm volatile("ldmatrix.sync.aligned.m8n8.x4.shared.b16 {%0,%1,%2,%3},[%4];" \
    : "=r"((r)[0]),"=r"((r)[1]),"=r"((r)[2]),"=r"((r)[3]) : "r"(addr))

#define MMA4(c,a,b0,b1) \
  asm volatile("mma.sync.aligned.m16n8k16.row.col.f32.bf16.bf16.f32 " \
    "{%0,%1,%2,%3},{%4,%5,%6,%7},{%8,%9},{%0,%1,%2,%3};" \
    : "+f"((c)[0]),"+f"((c)[1]),"+f"((c)[2]),"+f"((c)[3]) \
    : "r"((a)[0]),"r"((a)[1]),"r"((a)[2]),"r"((a)[3]),"r"(b0),"r"(b1))

// ---------------- kernel 0: fold We through W1's hE block ----------------
__global__ void k_fold(const float* __restrict__ Wew,const float* __restrict__ Web,
                       const float* __restrict__ W1w,const float* __restrict__ W1b){
  int j=threadIdx.x; int kb=blockIdx.x;
  if(kb<16){
    float s=0.f;
    for(int m=0;m<128;m++) s+=Wew[kb*128+m]*W1w[(128+m)*128+j];
    g_Wef[kb*128+j]=s;
  }else{
    float s=W1b[j];
    for(int m=0;m<128;m++) s+=Web[m]*W1w[(128+m)*128+j];
    g_bef[j]=s;
  }
}

// ---------------- kernel 1: node geometry + hV + HMMA Apre/Cpre ----------------
__global__ __launch_bounds__(256) void k_node(
    const float* __restrict__ X,const float* __restrict__ Wvw,
    const float* __restrict__ Wvb,const float* __restrict__ W1w){
  __shared__ float sfeat[32][21];
  __shared__ float sQ[32][9];
  __shared__ float shv[32][128];
  __shared__ __align__(16) char shvhi[32*SP*2];
  __shared__ __align__(16) char shvlo[32*SP*2];
  int t=threadIdx.x, w=t>>5, lane=t&31;
  int base=blockIdx.x*32;

  if(t<96){
    int nl=t/3, c=t-nl*3; int g=base+nl; int b=g>>11, n=g&(NN-1);
    int tt=3*n+c-1;
    float cD=1.f,sD=0.f,cA=1.f,sA=0.f;
    if(tt>=0 && tt<=3*NN-4){
      F3 x0=loadXf(X,b,tt),x1=loadXf(X,b,tt+1),x2=loadXf(X,b,tt+2),x3=loadXf(X,b,tt+3);
      F3 u0=norm3(sub3(x1,x0)),u1=norm3(sub3(x2,x1)),u2=norm3(sub3(x3,x2));
      F3 n0=norm3(cross3(u0,u1)),n1=norm3(cross3(u1,u2));
      float cd=clip1(dot3(n0,n1));
      F3 v=norm3(cross3(n0,n1));
      float sg=sgnf(-dot3(v,u1));
      cD=(sg==0.f)?1.f:cd;
      sD=sg*sqrtf(fmaxf(0.f,1.f-cd*cd));
      float ca=clip1(dot3(u0,u1));
      cA=ca; sA=sqrtf(fmaxf(0.f,1.f-ca*ca));
    }
    sfeat[nl][c]=cD; sfeat[nl][3+c]=sD; sfeat[nl][6+c]=cA; sfeat[nl][9+c]=sA;
  }else if(t<128){
    int nl=t-96; int g=base+nl; int b=g>>11, n=g&(NN-1);
    float Qr[9];
    if(n==NN-1){
      #pragma unroll
      for(int k2=0;k2<9;k2++)Qr[k2]=0.f;
    }else{
      F3 x0=loadXf(X,b,3*n),x1=loadXf(X,b,3*n+1),x2=loadXf(X,b,3*n+2);
      F3 u0=norm3(sub3(x1,x0)),u1=norm3(sub3(x2,x1));
      F3 n0=norm3(cross3(u0,u1)),b1=norm3(sub3(u0,u1));
      F3 r2=cross3(b1,n0);
      Qr[0]=b1.x;Qr[1]=b1.y;Qr[2]=b1.z;
      Qr[3]=n0.x;Qr[4]=n0.y;Qr[5]=n0.z;
      Qr[6]=r2.x;Qr[7]=r2.y;Qr[8]=r2.z;
    }
    #pragma unroll
    for(int k2=0;k2<9;k2++){sQ[nl][k2]=Qr[k2];g_Q[g*9+k2]=Qr[k2];}
  }
  __syncthreads();
  if(t<96){
    int nl=t/3, a=t-nl*3; int g=base+nl; int b=g>>11, n=g&(NN-1);
    int atom=(a==0)?0:(a+1);
    const float* Xp=X+((b*NN+n)*4)*3;
    F3 d=f3(Xp[atom*3]-Xp[0],Xp[atom*3+1]-Xp[1],Xp[atom*3+2]-Xp[2]);
    F3 du=f3(sQ[nl][0]*d.x+sQ[nl][1]*d.y+sQ[nl][2]*d.z,
             sQ[nl][3]*d.x+sQ[nl][4]*d.y+sQ[nl][5]*d.z,
             sQ[nl][6]*d.x+sQ[nl][7]*d.y+sQ[nl][8]*d.z);
    du=norm3(du);
    sfeat[nl][12+a*3+0]=du.x; sfeat[nl][12+a*3+1]=du.y; sfeat[nl][12+a*3+2]=du.z;
  }
  __syncthreads();
  {
    int j=t&127, half=t>>7;
    float wv[21];
    #pragma unroll
    for(int i=0;i<21;i++) wv[i]=Wvw[i*128+j];
    float bv=Wvb[j];
    for(int r=0;r<16;r++){
      int nl=half*16+r;
      float a=bv;
      #pragma unroll
      for(int i=0;i<21;i++) a+=sfeat[nl][i]*wv[i];
      shv[nl][j]=a;
      g_hV[(size_t)(base+nl)*128+j]=a;
    }
  }
  __syncthreads();
  for(int idx=t; idx<2048; idx+=256){
    int row=idx>>6, cp=idx&63;
    float a=shv[row][cp*2], bq=shv[row][cp*2+1];
    uint32_t hi,lo; split2(a,bq,hi,lo);
    *(uint32_t*)(shvhi+(size_t)(row*SP+cp*2)*2)=hi;
    *(uint32_t*)(shvlo+(size_t)(row*SP+cp*2)*2)=lo;
  }
  __syncthreads();
  {
    uint32_t hibase=smem_u32(shvhi), lobase=smem_u32(shvlo);
    uint32_t a_off=(uint32_t)(((lane&15)*SP+((lane>>4)<<3))*2);
    bool isA=(w<4);
    #pragma unroll
    for(int nt2=0;nt2<4;nt2++){
      int n0=w*32+nt2*8;
      int col=n0+(lane>>2);
      int ccol=isA?col:(col-128);
      int rbase=isA?0:256;
      uint32_t fhi[8][2], flo[8][2];
      #pragma unroll
      for(int ks=0;ks<8;ks++)
        #pragma unroll
        for(int p=0;p<2;p++){
          int k0=ks*16+(lane&3)*2+p*8;
          float wa=W1w[(size_t)(rbase+k0)*128+ccol];
          float wb=W1w[(size_t)(rbase+k0+1)*128+ccol];
          split2(wa,wb,fhi[ks][p],flo[ks][p]);
        }
      #pragma unroll
      for(int Mt=0;Mt<2;Mt++){
        float c[4]={0,0,0,0};
        uint32_t abase=a_off+(uint32_t)(Mt*16*SP*2);
        #pragma unroll
        for(int ks=0;ks<8;ks++){
          uint32_t ah[4],al[4];
          LDM4(ah, hibase+abase+ks*32);
          LDM4(al, lobase+abase+ks*32);
          MMA4(c,ah,fhi[ks][0],fhi[ks][1]);
          MMA4(c,ah,flo[ks][0],flo[ks][1]);
          MMA4(c,al,fhi[ks][0],fhi[ks][1]);
        }
        int m0=Mt*16+(lane>>2), m1=m0+8;
        int cc0=(isA?n0:(n0-128))+(lane&3)*2;
        float* dst=isA?g_Apre:g_Cpre;
        float2 p0; p0.x=c[0]; p0.y=c[1];
        float2 p1; p1.x=c[2]; p1.y=c[3];
        *(float2*)&dst[(size_t)(base+m0)*128+cc0]=p0;
        *(float2*)&dst[(size_t)(base+m1)*128+cc0]=p1;
      }
    }
  }
}

// ---------------- kernel 2: full-HMMA edge MLP + msg + LN1 ----------------
#define OFF_H1HI  0
#define OFF_H1LO  34816
#define OFF_E16HI 69632
#define OFF_E16LO 75776
#define OFF_APB   81920
#define OFF_NBR   83968
#define OFF_SG2   84480
#define OFF_SY    86528
#define OFF_SPART 88640
#define EDGE_SMEM_BYTES 92736

__global__ __launch_bounds__(256,2) void k_edge(
    const float* __restrict__ X,const int* __restrict__ Eidx,
    const float* __restrict__ W2w,const float* __restrict__ W2b,
    const float* __restrict__ W3w,const float* __restrict__ W3b,
    const float* __restrict__ l1g,const float* __restrict__ l1b){
  extern __shared__ __align__(16) char smc[];
  uint32_t sbase=smem_u32(smc);
  float* sApb=(float*)(smc+OFF_APB);
  int*   snbr=(int*)(smc+OFF_NBR);
  float* sg2 =(float*)(smc+OFF_SG2);
  float* sy  =(float*)(smc+OFF_SY);
  float* spart=(float*)(smc+OFF_SPART);
  int t=threadIdx.x, w=t>>5, lane=t&31;
  int wbase=w*16;

  uint32_t w2hi[2][8][2], w2lo[2][8][2];
  {
    int n=wbase+(lane>>2);
    #pragma unroll
    for(int nt=0;nt<2;nt++)
      #pragma unroll
      for(int ks=0;ks<8;ks++)
        #pragma unroll
        for(int p=0;p<2;p++){
          int k0=ks*16+(lane&3)*2+p*8;
          float wa=W2w[k0*128+n+nt*8], wb=W2w[(k0+1)*128+n+nt*8];
          split2(wa,wb,w2hi[nt][ks][p],w2lo[nt][ks][p]);
        }
  }
  float b2v[2][2];
  #pragma unroll
  for(int nt=0;nt<2;nt++){
    b2v[nt][0]=W2b[wbase+nt*8+(lane&3)*2];
    b2v[nt][1]=W2b[wbase+nt*8+(lane&3)*2+1];
  }

  for(int tile=blockIdx.x; tile<NTILES; tile+=gridDim.x){
    int node_base=tile*4;
    int b=node_base>>11;

    // ---- phase 1: edge geometry -> e16 bf16 hi/lo ; Apre staging ----
    if(t<128){
      int nl=t>>5, slot=t&31; int g=node_base+nl; int n=g&(NN-1);
      int nbr=(slot<KK)?Eidx[g*KK+slot]:0;
      snbr[t]=nbr;
      char* ehi=smc+OFF_E16HI+(size_t)t*48;
      char* elo=smc+OFF_E16LO+(size_t)t*48;
      if(slot<KK){
        float out[16];
        const float* Qo=g_Q+g*9;
        F3 q0=f3(Qo[0],Qo[1],Qo[2]),q1=f3(Qo[3],Qo[4],Qo[5]),q2=f3(Qo[6],Qo[7],Qo[8]);
        const float* Xo=X+(size_t)(b*NN+n)*12;
        F3 xa=f3(Xo[0],Xo[1],Xo[2]);
        const float* Xn=X+(size_t)(b*NN+nbr)*12;
        const int ord[4]={1,0,2,3};
        #pragma unroll
        for(int a=0;a<4;a++){
          int atom=ord[a];
          F3 p=f3(Xn[atom*3],Xn[atom*3+1],Xn[atom*3+2]);
          F3 d=sub3(p,xa);
          F3 du=norm3(f3(dot3(q0,d),dot3(q1,d),dot3(q2,d)));
          out[a*3]=du.x; out[a*3+1]=du.y; out[a*3+2]=du.z;
        }
        const float* Qn=g_Q+(size_t)(b*NN+nbr)*9;
        float R00=q0.x*Qn[0]+q1.x*Qn[3]+q2.x*Qn[6];
        float R01=q0.x*Qn[1]+q1.x*Qn[4]+q2.x*Qn[7];
        float R02=q0.x*Qn[2]+q1.x*Qn[5]+q2.x*Qn[8];
        float R10=q0.y*Qn[0]+q1.y*Qn[3]+q2.y*Qn[6];
        float R11=q0.y*Qn[1]+q1.y*Qn[4]+q2.y*Qn[7];
        float R12=q0.y*Qn[2]+q1.y*Qn[5]+q2.y*Qn[8];
        float R20=q0.z*Qn[0]+q1.z*Qn[3]+q2.z*Qn[6];
        float R21=q0.z*Qn[1]+q1.z*Qn[4]+q2.z*Qn[7];
        float R22=q0.z*Qn[2]+q1.z*Qn[5]+q2.z*Qn[8];
        float m0=0.5f*sqrtf(fabsf(1.f+R00-R11-R22));
        float m1=0.5f*sqrtf(fabsf(1.f-R00+R11-R22));
        float m2=0.5f*sqrtf(fabsf(1.f-R00-R11+R22));
        float qx=sgnf(R21-R12)*m0;
        float qy=sgnf(R02-R20)*m1;
        float qz=sgnf(R10-R01)*m2;
        float qw=0.5f*sqrtf(fmaxf(0.f,1.f+R00+R11+R22));
        float nq=qx*qx+qy*qy+qz*qz+qw*qw;
        if(nq>0.f){float r=rsqrtf(nq);qx*=r;qy*=r;qz*=r;qw*=r;}
        else{qx=0.f;qy=0.f;qz=0.f;qw=0.f;}
        out[12]=qx;out[13]=qy;out[14]=qz;out[15]=qw;
        uint4 h0,l0,h1,l1;
        split2(out[0],out[1],h0.x,l0.x);  split2(out[2],out[3],h0.y,l0.y);
        split2(out[4],out[5],h0.z,l0.z);  split2(out[6],out[7],h0.w,l0.w);
        split2(out[8],out[9],h1.x,l1.x);  split2(out[10],out[11],h1.y,l1.y);
        split2(out[12],out[13],h1.z,l1.z);split2(out[14],out[15],h1.w,l1.w);
        *(uint4*)(ehi)=h0;    *(uint4*)(ehi+16)=h1;
        *(uint4*)(elo)=l0;    *(uint4*)(elo+16)=l1;
      }else{
        uint4 z=make_uint4(0,0,0,0);
        *(uint4*)(ehi)=z; *(uint4*)(ehi+16)=z;
        *(uint4*)(elo)=z; *(uint4*)(elo+16)=z;
      }
    }
    {
      int i0=t, i1=t+256;
      sApb[i0]=g_Apre[(size_t)node_base*128+i0]+g_bef[i0&127];
      sApb[i1]=g_Apre[(size_t)node_base*128+i1]+g_bef[i1&127];
    }
    __syncthreads();

    // ---- phase 2: layer-1 MMA (K=16) + Apre/Cpre/gelu -> h1 hi/lo ----
    {
      uint32_t wefhi[2][2], weflo[2][2];
      {
        int n=wbase+(lane>>2);
        #pragma unroll
        for(int nt=0;nt<2;nt++)
          #pragma unroll
          for(int p=0;p<2;p++){
            int k0=(lane&3)*2+p*8;
            float wa=g_Wef[k0*128+n+nt*8], wb=g_Wef[(k0+1)*128+n+nt*8];
            split2(wa,wb,wefhi[nt][p],weflo[nt][p]);
          }
      }
      uint32_t a_off16=(uint32_t)((lane&15)*48+(lane>>4)*16);
      for(int Mt=0;Mt<8;Mt++){
        float c[2][4]={{0,0,0,0},{0,0,0,0}};
        uint32_t ah[4],al[4];
        LDM4(ah, sbase+OFF_E16HI+a_off16+(uint32_t)(Mt*16*48));
        LDM4(al, sbase+OFF_E16LO+a_off16+(uint32_t)(Mt*16*48));
        #pragma unroll
        for(int nt=0;nt<2;nt++){
          MMA4(c[nt],ah,wefhi[nt][0],wefhi[nt][1]);
          MMA4(c[nt],ah,weflo[nt][0],weflo[nt][1]);
          MMA4(c[nt],al,wefhi[nt][0],wefhi[nt][1]);
        }
        int m0=Mt*16+(lane>>2), m1=m0+8;
        int node=Mt>>1;
        bool k0=(m0&31)<KK, k1=(m1&31)<KK;
        const float* cp0p=g_Cpre+(size_t)(b*NN+snbr[m0])*128;
        const float* cp1p=g_Cpre+(size_t)(b*NN+snbr[m1])*128;
        #pragma unroll
        for(int nt=0;nt<2;nt++){
          int n0=wbase+nt*8+(lane&3)*2;
          float2 ap=*(const float2*)&sApb[node*128+n0];
          float2 cp0=*(const float2*)&cp0p[n0];
          float2 cp1=*(const float2*)&cp1p[n0];
          float v0=k0?gelu(c[nt][0]+ap.x+cp0.x):0.f;
          float v1=k0?gelu(c[nt][1]+ap.y+cp0.y):0.f;
          float v2=k1?gelu(c[nt][2]+ap.x+cp1.x):0.f;
          float v3=k1?gelu(c[nt][3]+ap.y+cp1.y):0.f;
          uint32_t hi,lo;
          split2(v0,v1,hi,lo);
          *(uint32_t*)(smc+OFF_H1HI+(size_t)(m0*SP+n0)*2)=hi;
          *(uint32_t*)(smc+OFF_H1LO+(size_t)(m0*SP+n0)*2)=lo;
          split2(v2,v3,hi,lo);
          *(uint32_t*)(smc+OFF_H1HI+(size_t)(m1*SP+n0)*2)=hi;
          *(uint32_t*)(smc+OFF_H1LO+(size_t)(m1*SP+n0)*2)=lo;
        }
      }
    }
    __syncthreads();

    // ---- phase 3: layer-2 MMA + in-register node reduction -> sg2 ----
    {
      float acc[4][2][2];
      #pragma unroll
      for(int nd=0;nd<4;nd++)
        #pragma unroll
        for(int nt=0;nt<2;nt++){acc[nd][nt][0]=0.f;acc[nd][nt][1]=0.f;}
      uint32_t a_off=(uint32_t)(((lane&15)*SP+((lane>>4)<<3))*2);
      for(int Mt=0;Mt<8;Mt++){
        float c[2][4]={{0,0,0,0},{0,0,0,0}};
        uint32_t abase=a_off+(uint32_t)(Mt*16*SP*2);
        #pragma unroll
        for(int ks=0;ks<8;ks++){
          uint32_t ah[4],al[4];
          LDM4(ah, sbase+OFF_H1HI+abase+ks*32);
          LDM4(al, sbase+OFF_H1LO+abase+ks*32);
          #pragma unroll
          for(int nt=0;nt<2;nt++){
            MMA4(c[nt],ah,w2hi[nt][ks][0],w2hi[nt][ks][1]);
            MMA4(c[nt],ah,w2lo[nt][ks][0],w2lo[nt][ks][1]);
            MMA4(c[nt],al,w2hi[nt][ks][0],w2hi[nt][ks][1]);
          }
        }
        int m0=Mt*16+(lane>>2), m1=m0+8;
        int node=Mt>>1;
        bool k0=(m0&31)<KK, k1=(m1&31)<KK;
        #pragma unroll
        for(int nt=0;nt<2;nt++){
          float v0=k0?gelu(c[nt][0]+b2v[nt][0]):0.f;
          float v1=k0?gelu(c[nt][1]+b2v[nt][1]):0.f;
          float v2=k1?gelu(c[nt][2]+b2v[nt][0]):0.f;
          float v3=k1?gelu(c[nt][3]+b2v[nt][1]):0.f;
          acc[node][nt][0]+=v0+v2;
          acc[node][nt][1]+=v1+v3;
        }
      }
      #pragma unroll
      for(int nd=0;nd<4;nd++)
        #pragma unroll
        for(int nt=0;nt<2;nt++)
          #pragma unroll
          for(int cp=0;cp<2;cp++){
            float v=acc[nd][nt][cp];
            v+=__shfl_xor_sync(0xffffffffu,v,4);
            v+=__shfl_xor_sync(0xffffffffu,v,8);
            v+=__shfl_xor_sync(0xffffffffu,v,16);
            acc[nd][nt][cp]=v;
          }
      if(lane<4){
        #pragma unroll
        for(int nd=0;nd<4;nd++)
          #pragma unroll
          for(int nt=0;nt<2;nt++){
            sg2[nd*128+wbase+nt*8+lane*2  ]=acc[nd][nt][0];
            sg2[nd*128+wbase+nt*8+lane*2+1]=acc[nd][nt][1];
          }
      }
    }
    __syncthreads();

    // ---- phase 4: msg = g2@W3, K-split across 2 halves ----
    {
      int j=t&127, kh=t>>7;
      const float* wp=W3w+(size_t)(kh*64)*128+j;
      float a0=0.f,a1=0.f,a2=0.f,a3=0.f;
      int ib=kh*64;
      #pragma unroll 4
      for(int i=0;i<64;i++){
        float wv=wp[(size_t)i*128];
        int ii=ib+i;
        a0+=sg2[0*128+ii]*wv; a1+=sg2[1*128+ii]*wv;
        a2+=sg2[2*128+ii]*wv; a3+=sg2[3*128+ii]*wv;
      }
      float* sp=spart+kh*512;
      sp[0*128+j]=a0; sp[1*128+j]=a1; sp[2*128+j]=a2; sp[3*128+j]=a3;
    }
    __syncthreads();
    {
      #pragma unroll
      for(int o=0;o<2;o++){
        int oo=t+o*256; int nd=oo>>7, j=oo&127;
        float m=(spart[nd*128+j]+spart[512+nd*128+j])*(1.f/(float)KK)+W3b[j];
        sy[nd*132+j]=g_hV[(size_t)(node_base+nd)*128+j]+m;
      }
    }
    __syncthreads();

    // ---- phase 5: LN1 (warp per node) -> g_hV1 ----
    if(w<4){
      float4 v=*(const float4*)&sy[w*132+lane*4];
      float s=v.x+v.y+v.z+v.w;
      #pragma unroll
      for(int o=16;o;o>>=1) s+=__shfl_xor_sync(0xffffffffu,s,o);
      float m=s*(1.f/128.f);
      float dx=v.x-m,dy=v.y-m,dz=v.z-m,dw=v.w-m;
      float q=dx*dx+dy*dy+dz*dz+dw*dw;
      #pragma unroll
      for(int o=16;o;o>>=1) q+=__shfl_xor_sync(0xffffffffu,q,o);
      float rs=rsqrtf(q*(1.f/128.f)+1e-5f);
      float4 gg=*(const float4*)&l1g[lane*4];
      float4 bb=*(const float4*)&l1b[lane*4];
      float4 o4;
      o4.x=dx*rs*gg.x+bb.x; o4.y=dy*rs*gg.y+bb.y;
      o4.z=dz*rs*gg.z+bb.z; o4.w=dw*rs*gg.w+bb.w;
      *(float4*)&g_hV1[(size_t)(node_base+w)*128+lane*4]=o4;
    }
    __syncthreads();
  }
}

// ---------------- kernel 3: HMMA FF + LN2, M=32/block, 2 CTA/SM ----------------
#define FF2_AHI 0
#define FF2_ALO 8704
#define FF2_HHI 17408
#define FF2_HLO 26112
#define FF2_Y   34816
#define FF2_SMEM 51712

__global__ __launch_bounds__(256,2) void k_ff2(
    const float* __restrict__ Wi,const float* __restrict__ bi,
    const float* __restrict__ Wo,const float* __restrict__ bo,
    const float* __restrict__ l2g,const float* __restrict__ l2b,
    float* __restrict__ out){
  extern __shared__ __align__(16) char smc[];
  uint32_t sbase=smem_u32(smc);
  float* sy=(float*)(smc+FF2_Y);
  int t=threadIdx.x, w=t>>5, lane=t&31;
  int base=blockIdx.x*32;

  for(int idx=t; idx<2048; idx+=256){
    int row=idx>>6, cp=idx&63;
    float2 v=*(const float2*)&g_hV1[(size_t)(base+row)*128+cp*2];
    uint32_t hi,lo; split2(v.x,v.y,hi,lo);
    *(uint32_t*)(smc+FF2_AHI+(size_t)(row*SP+cp*2)*2)=hi;
    *(uint32_t*)(smc+FF2_ALO+(size_t)(row*SP+cp*2)*2)=lo;
  }
  __syncthreads();

  float C[2][2][4];
  #pragma unroll
  for(int Mt=0;Mt<2;Mt++)
    #pragma unroll
    for(int nt=0;nt<2;nt++)
      #pragma unroll
      for(int q=0;q<4;q++) C[Mt][nt][q]=0.f;

  uint32_t a_off=(uint32_t)(((lane&15)*SP+((lane>>4)<<3))*2);

  for(int ch=0;ch<4;ch++){
    // ---- GEMM1: load BOTH nt fragment sets, then share A loads ----
    {
      uint32_t fhi[2][8][2], flo[2][8][2];
      #pragma unroll
      for(int nt=0;nt<2;nt++){
        int n=ch*128+w*16+nt*8+(lane>>2);
        #pragma unroll
        for(int ks=0;ks<8;ks++)
          #pragma unroll
          for(int p=0;p<2;p++){
            int k0=ks*16+(lane&3)*2+p*8;
            float wa=Wi[(size_t)k0*512+n], wb=Wi[(size_t)(k0+1)*512+n];
            split2(wa,wb,fhi[nt][ks][p],flo[nt][ks][p]);
          }
      }
      float bi0[2],bi1[2];
      #pragma unroll
      for(int nt=0;nt<2;nt++){
        bi0[nt]=bi[ch*128+w*16+nt*8+(lane&3)*2];
        bi1[nt]=bi[ch*128+w*16+nt*8+(lane&3)*2+1];
      }
      #pragma unroll
      for(int Mt=0;Mt<2;Mt++){
        float c[2][4]={{0,0,0,0},{0,0,0,0}};
        uint32_t abase=a_off+(uint32_t)(Mt*16*SP*2);
        #pragma unroll
        for(int ks=0;ks<8;ks++){
          uint32_t ah[4],al[4];
          LDM4(ah, sbase+FF2_AHI+abase+ks*32);
          LDM4(al, sbase+FF2_ALO+abase+ks*32);
          #pragma unroll
          for(int nt=0;nt<2;nt++){
            MMA4(c[nt],ah,fhi[nt][ks][0],fhi[nt][ks][1]);
            MMA4(c[nt],ah,flo[nt][ks][0],flo[nt][ks][1]);
            MMA4(c[nt],al,fhi[nt][ks][0],fhi[nt][ks][1]);
          }
        }
        int m0=Mt*16+(lane>>2), m1=m0+8;
        #pragma unroll
        for(int nt=0;nt<2;nt++){
          int n0=w*16+nt*8+(lane&3)*2;
          uint32_t hi,lo;
          split2(gelu(c[nt][0]+bi0[nt]),gelu(c[nt][1]+bi1[nt]),hi,lo);
          *(uint32_t*)(smc+FF2_HHI+(size_t)(m0*SP+n0)*2)=hi;
          *(uint32_t*)(smc+FF2_HLO+(size_t)(m0*SP+n0)*2)=lo;
          split2(gelu(c[nt][2]+bi0[nt]),gelu(c[nt][3]+bi1[nt]),hi,lo);
          *(uint32_t*)(smc+FF2_HHI+(size_t)(m1*SP+n0)*2)=hi;
          *(uint32_t*)(smc+FF2_HLO+(size_t)(m1*SP+n0)*2)=lo;
        }
      }
    }
    __syncthreads();

    // ---- GEMM2: load BOTH nt fragment sets, then share A loads ----
    {
      uint32_t fhi[2][8][2], flo[2][8][2];
      #pragma unroll
      for(int nt=0;nt<2;nt++){
        int n=w*16+nt*8+(lane>>2);
        #pragma unroll
        for(int ks=0;ks<8;ks++)
          #pragma unroll
          for(int p=0;p<2;p++){
            int k0=ch*128+ks*16+(lane&3)*2+p*8;
            float wa=Wo[(size_t)k0*128+n], wb=Wo[(size_t)(k0+1)*128+n];
            split2(wa,wb,fhi[nt][ks][p],flo[nt][ks][p]);
          }
      }
      #pragma unroll
      for(int Mt=0;Mt<2;Mt++){
        uint32_t abase=a_off+(uint32_t)(Mt*16*SP*2);
        #pragma unroll
        for(int ks=0;ks<8;ks++){
          uint32_t ah[4],al[4];
          LDM4(ah, sbase+FF2_HHI+abase+ks*32);
          LDM4(al, sbase+FF2_HLO+abase+ks*32);
          #pragma unroll
          for(int nt=0;nt<2;nt++){
            MMA4(C[Mt][nt],ah,fhi[nt][ks][0],fhi[nt][ks][1]);
            MMA4(C[Mt][nt],ah,flo[nt][ks][0],flo[nt][ks][1]);
            MMA4(C[Mt][nt],al,fhi[nt][ks][0],fhi[nt][ks][1]);
          }
        }
      }
    }
    __syncthreads();
  }

  {
    #pragma unroll
    for(int Mt=0;Mt<2;Mt++){
      int m0=Mt*16+(lane>>2), m1=m0+8;
      #pragma unroll
      for(int nt=0;nt<2;nt++){
        int n0=w*16+nt*8+(lane&3)*2;
        float b0=bo[n0], b1=bo[n0+1];
        sy[m0*132+n0  ]=C[Mt][nt][0]+b0+g_hV1[(size_t)(base+m0)*128+n0];
        sy[m0*132+n0+1]=C[Mt][nt][1]+b1+g_hV1[(size_t)(base+m0)*128+n0+1];
        sy[m1*132+n0  ]=C[Mt][nt][2]+b0+g_hV1[(size_t)(base+m1)*128+n0];
        sy[m1*132+n0+1]=C[Mt][nt][3]+b1+g_hV1[(size_t)(base+m1)*128+n0+1];
      }
    }
  }
  __syncthreads();
  for(int r=0;r<4;r++){
    int row=w*4+r;
    float4 v=*(const float4*)&sy[row*132+lane*4];
    float s=v.x+v.y+v.z+v.w;
    #pragma unroll
    for(int o=16;o;o>>=1) s+=__shfl_xor_sync(0xffffffffu,s,o);
    float m=s*(1.f/128.f);
    float dx=v.x-m,dy=v.y-m,dz=v.z-m,dw=v.w-m;
    float q=dx*dx+dy*dy+dz*dz+dw*dw;
    #pragma unroll
    for(int o=16;o;o>>=1) q+=__shfl_xor_sync(0xffffffffu,q,o);
    float rs=rsqrtf(q*(1.f/128.f)+1e-5f);
    float4 gg=*(const float4*)&l2g[lane*4];
    float4 bb=*(const float4*)&l2b[lane*4];
    float4 o4;
    o4.x=dx*rs*gg.x+bb.x; o4.y=dy*rs*gg.y+bb.y;
    o4.z=dz*rs*gg.z+bb.z; o4.w=dw*rs*gg.w+bb.w;
    *(float4*)&out[(size_t)(base+row)*128+lane*4]=o4;
  }
}

// ---------------- launch ----------------
extern "C" void kernel_launch(void* const* d_in, const int* in_sizes, int n_in,
                              void* d_out, int out_size){
  const float* X  =(const float*)d_in[0];
  const int*  Eidx=(const int*  )d_in[1];
  const float* Wvw=(const float*)d_in[2];
  const float* Wvb=(const float*)d_in[3];
  const float* Wew=(const float*)d_in[4];
  const float* Web=(const float*)d_in[5];
  const float* W1w=(const float*)d_in[6];
  const float* W1b=(const float*)d_in[7];
  const float* W2w=(const float*)d_in[8];
  const float* W2b=(const float*)d_in[9];
  const float* W3w=(const float*)d_in[10];
  const float* W3b=(const float*)d_in[11];
  const float* Wiw=(const float*)d_in[12];
  const float* Wib=(const float*)d_in[13];
  const float* Wow=(const float*)d_in[14];
  const float* Wob=(const float*)d_in[15];
  const float* l1g=(const float*)d_in[16];
  const float* l1b=(const float*)d_in[17];
  const float* l2g=(const float*)d_in[18];
  const float* l2b=(const float*)d_in[19];
  float* out=(float*)d_out;

  cudaFuncSetAttribute(k_edge, cudaFuncAttributeMaxDynamicSharedMemorySize,
                       EDGE_SMEM_BYTES);
  cudaFuncSetAttribute(k_ff2, cudaFuncAttributeMaxDynamicSharedMemorySize,
                       FF2_SMEM);

  k_fold<<<17,128>>>(Wew,Web,W1w,W1b);
  k_node<<<NNODES/32,256>>>(X,Wvw,Wvb,W1w);
  k_edge<<<296,256,EDGE_SMEM_BYTES>>>(X,Eidx,W2w,W2b,W3w,W3b,l1g,l1b);
  k_ff2<<<NNODES/32,256,FF2_SMEM>>>(Wiw,Wib,Wow,Wob,l2g,l2b,out);
}

// round 16
// speedup vs baseline: 1.0706x; 1.0438x over previous
#include <cuda_runtime.h>
#include <cuda_bf16.h>
#include <math.h>
#include <stdint.h>

#define BB 4
#define NN 2048
#define KK 30
#define HH 128
#define NNODES (BB*NN)
#define NTILES (NNODES/4)
#define SP 136          // padded bf16 row stride for 128-col MMA activation buffers

// ---------------- device scratch ----------------
__device__ __align__(16) float g_hV  [NNODES*HH];
__device__ __align__(16) float g_Apre[NNODES*HH];
__device__ __align__(16) float g_Cpre[NNODES*HH];
__device__ __align__(16) float g_Q   [NNODES*9];
__device__ __align__(16) float g_hV1 [NNODES*HH];
__device__ __align__(16) float g_Wef [16*HH];
__device__ __align__(16) float g_bef [HH];

// ---------------- geometry helpers ----------------
struct F3{float x,y,z;};
__device__ __forceinline__ F3 f3(float a,float b,float c){F3 r;r.x=a;r.y=b;r.z=c;return r;}
__device__ __forceinline__ F3 sub3(F3 a,F3 b){return f3(a.x-b.x,a.y-b.y,a.z-b.z);}
__device__ __forceinline__ float dot3(F3 a,F3 b){return a.x*b.x+a.y*b.y+a.z*b.z;}
__device__ __forceinline__ F3 cross3(F3 a,F3 b){
  return f3(a.y*b.z-a.z*b.y, a.z*b.x-a.x*b.z, a.x*b.y-a.y*b.x);
}
__device__ __forceinline__ F3 norm3(F3 v){
  float n=dot3(v,v);
  if(n>0.f){float r=rsqrtf(n);return f3(v.x*r,v.y*r,v.z*r);}
  return f3(0.f,0.f,0.f);
}
__device__ __forceinline__ float sgnf(float x){return (x>0.f)?1.f:((x<0.f)?-1.f:0.f);}
__device__ __forceinline__ float gelu(float x){return 0.5f*x*(1.f+erff(x*0.7071067811865475f));}
__device__ __forceinline__ float clip1(float x){return fminf(fmaxf(x,-1.f+1e-7f),1.f-1e-7f);}
__device__ __forceinline__ F3 loadXf(const float* X,int b,int f){
  const float* p=X+(((b*NN)+(f/3))*4+(f%3))*3;
  return f3(p[0],p[1],p[2]);
}

// ---------------- mma helpers ----------------
__device__ __forceinline__ uint32_t smem_u32(const void* p){
  uint32_t a;
  asm("{ .reg .u64 t; cvta.to.shared.u64 t, %1; cvt.u32.u64 %0, t; }":"=r"(a):"l"(p));
  return a;
}
// single-instruction packed f32x2 -> bf16x2 (low = a, high = b), rn rounding
__device__ __forceinline__ uint32_t pkbf(float a,float b){
  uint32_t r;
  asm("cvt.rn.bf16x2.f32 %0, %1, %2;" : "=r"(r) : "f"(b), "f"(a));
  return r;
}
// 6-instruction hi/lo split: hi = pack(bf(a),bf(b)); lo = pack(a-hi.a, b-hi.b)
__device__ __forceinline__ void split2(float a,float b,uint32_t&hi,uint32_t&lo){
  uint32_t h=pkbf(a,b);
  float ha=__uint_as_float(h<<16);
  float hb=__uint_as_float(h&0xffff0000u);
  lo=pkbf(a-ha,b-hb);
  hi=h;
}

#define LDM4(r,addr) \
  asm volatile("ldmatrix.sync.aligned.m8n8.x4.shared.b16 {%0,%1,%2,%3},[%4];" \
    : "=r"((r)[0]),"=r"((r)[1]),"=r"((r)[2]),"=r"((r)[3]) : "r"(addr))

#define MMA4(c,a,b0,b1) \
  asm volatile("mma.sync.aligned.m16n8k16.row.col.f32.bf16.bf16.f32 " \
    "{%0,%1,%2,%3},{%4,%5,%6,%7},{%8,%9},{%0,%1,%2,%3};" \
    : "+f"((c)[0]),"+f"((c)[1]),"+f"((c)[2]),"+f"((c)[3]) \
    : "r"((a)[0]),"r"((a)[1]),"r"((a)[2]),"r"((a)[3]),"r"(b0),"r"(b1))

// ---------------- kernel 0: fold We through W1's hE block ----------------
__global__ void k_fold(const float* __restrict__ Wew,const float* __restrict__ Web,
                       const float* __restrict__ W1w,const float* __restrict__ W1b){
  int j=threadIdx.x; int kb=blockIdx.x;
  if(kb<16){
    float s=0.f;
    for(int m=0;m<128;m++) s+=Wew[kb*128+m]*W1w[(128+m)*128+j];
    g_Wef[kb*128+j]=s;
  }else{
    float s=W1b[j];
    for(int m=0;m<128;m++) s+=Web[m]*W1w[(128+m)*128+j];
    g_bef[j]=s;
  }
}

// ---------------- kernel 1: node geometry + hV + HMMA Apre/Cpre ----------------
__global__ __launch_bounds__(256) void k_node(
    const float* __restrict__ X,const float* __restrict__ Wvw,
    const float* __restrict__ Wvb,const float* __restrict__ W1w){
  __shared__ float sfeat[32][21];
  __shared__ float sQ[32][9];
  __shared__ float shv[32][128];
  __shared__ __align__(16) char shvhi[32*SP*2];
  __shared__ __align__(16) char shvlo[32*SP*2];
  int t=threadIdx.x, w=t>>5, lane=t&31;
  int base=blockIdx.x*32;

  if(t<96){
    int nl=t/3, c=t-nl*3; int g=base+nl; int b=g>>11, n=g&(NN-1);
    int tt=3*n+c-1;
    float cD=1.f,sD=0.f,cA=1.f,sA=0.f;
    if(tt>=0 && tt<=3*NN-4){
      F3 x0=loadXf(X,b,tt),x1=loadXf(X,b,tt+1),x2=loadXf(X,b,tt+2),x3=loadXf(X,b,tt+3);
      F3 u0=norm3(sub3(x1,x0)),u1=norm3(sub3(x2,x1)),u2=norm3(sub3(x3,x2));
      F3 n0=norm3(cross3(u0,u1)),n1=norm3(cross3(u1,u2));
      float cd=clip1(dot3(n0,n1));
      F3 v=norm3(cross3(n0,n1));
      float sg=sgnf(-dot3(v,u1));
      cD=(sg==0.f)?1.f:cd;
      sD=sg*sqrtf(fmaxf(0.f,1.f-cd*cd));
      float ca=clip1(dot3(u0,u1));
      cA=ca; sA=sqrtf(fmaxf(0.f,1.f-ca*ca));
    }
    sfeat[nl][c]=cD; sfeat[nl][3+c]=sD; sfeat[nl][6+c]=cA; sfeat[nl][9+c]=sA;
  }else if(t<128){
    int nl=t-96; int g=base+nl; int b=g>>11, n=g&(NN-1);
    float Qr[9];
    if(n==NN-1){
      #pragma unroll
      for(int k2=0;k2<9;k2++)Qr[k2]=0.f;
    }else{
      F3 x0=loadXf(X,b,3*n),x1=loadXf(X,b,3*n+1),x2=loadXf(X,b,3*n+2);
      F3 u0=norm3(sub3(x1,x0)),u1=norm3(sub3(x2,x1));
      F3 n0=norm3(cross3(u0,u1)),b1=norm3(sub3(u0,u1));
      F3 r2=cross3(b1,n0);
      Qr[0]=b1.x;Qr[1]=b1.y;Qr[2]=b1.z;
      Qr[3]=n0.x;Qr[4]=n0.y;Qr[5]=n0.z;
      Qr[6]=r2.x;Qr[7]=r2.y;Qr[8]=r2.z;
    }
    #pragma unroll
    for(int k2=0;k2<9;k2++){sQ[nl][k2]=Qr[k2];g_Q[g*9+k2]=Qr[k2];}
  }
  __syncthreads();
  if(t<96){
    int nl=t/3, a=t-nl*3; int g=base+nl; int b=g>>11, n=g&(NN-1);
    int atom=(a==0)?0:(a+1);
    const float* Xp=X+((b*NN+n)*4)*3;
    F3 d=f3(Xp[atom*3]-Xp[0],Xp[atom*3+1]-Xp[1],Xp[atom*3+2]-Xp[2]);
    F3 du=f3(sQ[nl][0]*d.x+sQ[nl][1]*d.y+sQ[nl][2]*d.z,
             sQ[nl][3]*d.x+sQ[nl][4]*d.y+sQ[nl][5]*d.z,
             sQ[nl][6]*d.x+sQ[nl][7]*d.y+sQ[nl][8]*d.z);
    du=norm3(du);
    sfeat[nl][12+a*3+0]=du.x; sfeat[nl][12+a*3+1]=du.y; sfeat[nl][12+a*3+2]=du.z;
  }
  __syncthreads();
  {
    int j=t&127, half=t>>7;
    float wv[21];
    #pragma unroll
    for(int i=0;i<21;i++) wv[i]=Wvw[i*128+j];
    float bv=Wvb[j];
    for(int r=0;r<16;r++){
      int nl=half*16+r;
      float a=bv;
      #pragma unroll
      for(int i=0;i<21;i++) a+=sfeat[nl][i]*wv[i];
      shv[nl][j]=a;
      g_hV[(size_t)(base+nl)*128+j]=a;
    }
  }
  __syncthreads();
  for(int idx=t; idx<2048; idx+=256){
    int row=idx>>6, cp=idx&63;
    float a=shv[row][cp*2], bq=shv[row][cp*2+1];
    uint32_t hi,lo; split2(a,bq,hi,lo);
    *(uint32_t*)(shvhi+(size_t)(row*SP+cp*2)*2)=hi;
    *(uint32_t*)(shvlo+(size_t)(row*SP+cp*2)*2)=lo;
  }
  __syncthreads();
  {
    uint32_t hibase=smem_u32(shvhi), lobase=smem_u32(shvlo);
    uint32_t a_off=(uint32_t)(((lane&15)*SP+((lane>>4)<<3))*2);
    bool isA=(w<4);
    #pragma unroll
    for(int nt2=0;nt2<4;nt2++){
      int n0=w*32+nt2*8;
      int col=n0+(lane>>2);
      int ccol=isA?col:(col-128);
      int rbase=isA?0:256;
      uint32_t fhi[8][2], flo[8][2];
      #pragma unroll
      for(int ks=0;ks<8;ks++)
        #pragma unroll
        for(int p=0;p<2;p++){
          int k0=ks*16+(lane&3)*2+p*8;
          float wa=W1w[(size_t)(rbase+k0)*128+ccol];
          float wb=W1w[(size_t)(rbase+k0+1)*128+ccol];
          split2(wa,wb,fhi[ks][p],flo[ks][p]);
        }
      #pragma unroll
      for(int Mt=0;Mt<2;Mt++){
        float c[4]={0,0,0,0};
        uint32_t abase=a_off+(uint32_t)(Mt*16*SP*2);
        #pragma unroll
        for(int ks=0;ks<8;ks++){
          uint32_t ah[4],al[4];
          LDM4(ah, hibase+abase+ks*32);
          LDM4(al, lobase+abase+ks*32);
          MMA4(c,ah,fhi[ks][0],fhi[ks][1]);
          MMA4(c,ah,flo[ks][0],flo[ks][1]);
          MMA4(c,al,fhi[ks][0],fhi[ks][1]);
        }
        int m0=Mt*16+(lane>>2), m1=m0+8;
        int cc0=(isA?n0:(n0-128))+(lane&3)*2;
        float* dst=isA?g_Apre:g_Cpre;
        float2 p0; p0.x=c[0]; p0.y=c[1];
        float2 p1; p1.x=c[2]; p1.y=c[3];
        *(float2*)&dst[(size_t)(base+m0)*128+cc0]=p0;
        *(float2*)&dst[(size_t)(base+m1)*128+cc0]=p1;
      }
    }
  }
}

// ---------------- kernel 2: full-HMMA edge MLP + msg + LN1 ----------------
#define OFF_H1HI  0
#define OFF_H1LO  34816
#define OFF_E16HI 69632
#define OFF_E16LO 75776
#define OFF_APB   81920
#define OFF_NBR   83968
#define OFF_SG2   84480
#define OFF_SY    86528
#define OFF_SPART 88640
#define EDGE_SMEM_BYTES 92736

__global__ __launch_bounds__(256,2) void k_edge(
    const float* __restrict__ X,const int* __restrict__ Eidx,
    const float* __restrict__ W2w,const float* __restrict__ W2b,
    const float* __restrict__ W3w,const float* __restrict__ W3b,
    const float* __restrict__ l1g,const float* __restrict__ l1b){
  extern __shared__ __align__(16) char smc[];
  uint32_t sbase=smem_u32(smc);
  float* sApb=(float*)(smc+OFF_APB);
  int*   snbr=(int*)(smc+OFF_NBR);
  float* sg2 =(float*)(smc+OFF_SG2);
  float* sy  =(float*)(smc+OFF_SY);
  float* spart=(float*)(smc+OFF_SPART);
  int t=threadIdx.x, w=t>>5, lane=t&31;
  int wbase=w*16;

  uint32_t w2hi[2][8][2], w2lo[2][8][2];
  {
    int n=wbase+(lane>>2);
    #pragma unroll
    for(int nt=0;nt<2;nt++)
      #pragma unroll
      for(int ks=0;ks<8;ks++)
        #pragma unroll
        for(int p=0;p<2;p++){
          int k0=ks*16+(lane&3)*2+p*8;
          float wa=W2w[k0*128+n+nt*8], wb=W2w[(k0+1)*128+n+nt*8];
          split2(wa,wb,w2hi[nt][ks][p],w2lo[nt][ks][p]);
        }
  }
  float b2v[2][2];
  #pragma unroll
  for(int nt=0;nt<2;nt++){
    b2v[nt][0]=W2b[wbase+nt*8+(lane&3)*2];
    b2v[nt][1]=W2b[wbase+nt*8+(lane&3)*2+1];
  }

  for(int tile=blockIdx.x; tile<NTILES; tile+=gridDim.x){
    int node_base=tile*4;
    int b=node_base>>11;

    // ---- phase 1: edge geometry -> e16 bf16 hi/lo ; Apre staging ----
    if(t<128){
      int nl=t>>5, slot=t&31; int g=node_base+nl; int n=g&(NN-1);
      int nbr=(slot<KK)?Eidx[g*KK+slot]:0;
      snbr[t]=nbr;
      char* ehi=smc+OFF_E16HI+(size_t)t*48;
      char* elo=smc+OFF_E16LO+(size_t)t*48;
      if(slot<KK){
        float out[16];
        const float* Qo=g_Q+g*9;
        F3 q0=f3(Qo[0],Qo[1],Qo[2]),q1=f3(Qo[3],Qo[4],Qo[5]),q2=f3(Qo[6],Qo[7],Qo[8]);
        const float* Xo=X+(size_t)(b*NN+n)*12;
        F3 xa=f3(Xo[0],Xo[1],Xo[2]);
        const float* Xn=X+(size_t)(b*NN+nbr)*12;
        const int ord[4]={1,0,2,3};
        #pragma unroll
        for(int a=0;a<4;a++){
          int atom=ord[a];
          F3 p=f3(Xn[atom*3],Xn[atom*3+1],Xn[atom*3+2]);
          F3 d=sub3(p,xa);
          F3 du=norm3(f3(dot3(q0,d),dot3(q1,d),dot3(q2,d)));
          out[a*3]=du.x; out[a*3+1]=du.y; out[a*3+2]=du.z;
        }
        const float* Qn=g_Q+(size_t)(b*NN+nbr)*9;
        float R00=q0.x*Qn[0]+q1.x*Qn[3]+q2.x*Qn[6];
        float R01=q0.x*Qn[1]+q1.x*Qn[4]+q2.x*Qn[7];
        float R02=q0.x*Qn[2]+q1.x*Qn[5]+q2.x*Qn[8];
        float R10=q0.y*Qn[0]+q1.y*Qn[3]+q2.y*Qn[6];
        float R11=q0.y*Qn[1]+q1.y*Qn[4]+q2.y*Qn[7];
        float R12=q0.y*Qn[2]+q1.y*Qn[5]+q2.y*Qn[8];
        float R20=q0.z*Qn[0]+q1.z*Qn[3]+q2.z*Qn[6];
        float R21=q0.z*Qn[1]+q1.z*Qn[4]+q2.z*Qn[7];
        float R22=q0.z*Qn[2]+q1.z*Qn[5]+q2.z*Qn[8];
        float m0=0.5f*sqrtf(fabsf(1.f+R00-R11-R22));
        float m1=0.5f*sqrtf(fabsf(1.f-R00+R11-R22));
        float m2=0.5f*sqrtf(fabsf(1.f-R00-R11+R22));
        float qx=sgnf(R21-R12)*m0;
        float qy=sgnf(R02-R20)*m1;
        float qz=sgnf(R10-R01)*m2;
        float qw=0.5f*sqrtf(fmaxf(0.f,1.f+R00+R11+R22));
        float nq=qx*qx+qy*qy+qz*qz+qw*qw;
        if(nq>0.f){float r=rsqrtf(nq);qx*=r;qy*=r;qz*=r;qw*=r;}
        else{qx=0.f;qy=0.f;qz=0.f;qw=0.f;}
        out[12]=qx;out[13]=qy;out[14]=qz;out[15]=qw;
        uint4 h0,l0,h1,l1;
        split2(out[0],out[1],h0.x,l0.x);  split2(out[2],out[3],h0.y,l0.y);
        split2(out[4],out[5],h0.z,l0.z);  split2(out[6],out[7],h0.w,l0.w);
        split2(out[8],out[9],h1.x,l1.x);  split2(out[10],out[11],h1.y,l1.y);
        split2(out[12],out[13],h1.z,l1.z);split2(out[14],out[15],h1.w,l1.w);
        *(uint4*)(ehi)=h0;    *(uint4*)(ehi+16)=h1;
        *(uint4*)(elo)=l0;    *(uint4*)(elo+16)=l1;
      }else{
        uint4 z=make_uint4(0,0,0,0);
        *(uint4*)(ehi)=z; *(uint4*)(ehi+16)=z;
        *(uint4*)(elo)=z; *(uint4*)(elo+16)=z;
      }
    }
    {
      int i0=t, i1=t+256;
      sApb[i0]=g_Apre[(size_t)node_base*128+i0]+g_bef[i0&127];
      sApb[i1]=g_Apre[(size_t)node_base*128+i1]+g_bef[i1&127];
    }
    __syncthreads();

    // ---- phase 2: layer-1 MMA (K=16) + Apre/Cpre/gelu -> h1 hi/lo ----
    // Mt loop UNROLLED so ptxas can front-batch the scattered Cpre LDGs
    {
      uint32_t wefhi[2][2], weflo[2][2];
      {
        int n=wbase+(lane>>2);
        #pragma unroll
        for(int nt=0;nt<2;nt++)
          #pragma unroll
          for(int p=0;p<2;p++){
            int k0=(lane&3)*2+p*8;
            float wa=g_Wef[k0*128+n+nt*8], wb=g_Wef[(k0+1)*128+n+nt*8];
            split2(wa,wb,wefhi[nt][p],weflo[nt][p]);
          }
      }
      uint32_t a_off16=(uint32_t)((lane&15)*48+(lane>>4)*16);
      #pragma unroll
      for(int Mt=0;Mt<8;Mt++){
        float c[2][4]={{0,0,0,0},{0,0,0,0}};
        uint32_t ah[4],al[4];
        LDM4(ah, sbase+OFF_E16HI+a_off16+(uint32_t)(Mt*16*48));
        LDM4(al, sbase+OFF_E16LO+a_off16+(uint32_t)(Mt*16*48));
        #pragma unroll
        for(int nt=0;nt<2;nt++){
          MMA4(c[nt],ah,wefhi[nt][0],wefhi[nt][1]);
          MMA4(c[nt],ah,weflo[nt][0],weflo[nt][1]);
          MMA4(c[nt],al,wefhi[nt][0],wefhi[nt][1]);
        }
        int m0=Mt*16+(lane>>2), m1=m0+8;
        int node=Mt>>1;
        bool k0=(m0&31)<KK, k1=(m1&31)<KK;
        const float* cp0p=g_Cpre+(size_t)(b*NN+snbr[m0])*128;
        const float* cp1p=g_Cpre+(size_t)(b*NN+snbr[m1])*128;
        #pragma unroll
        for(int nt=0;nt<2;nt++){
          int n0=wbase+nt*8+(lane&3)*2;
          float2 ap=*(const float2*)&sApb[node*128+n0];
          float2 cp0=*(const float2*)&cp0p[n0];
          float2 cp1=*(const float2*)&cp1p[n0];
          float v0=k0?gelu(c[nt][0]+ap.x+cp0.x):0.f;
          float v1=k0?gelu(c[nt][1]+ap.y+cp0.y):0.f;
          float v2=k1?gelu(c[nt][2]+ap.x+cp1.x):0.f;
          float v3=k1?gelu(c[nt][3]+ap.y+cp1.y):0.f;
          uint32_t hi,lo;
          split2(v0,v1,hi,lo);
          *(uint32_t*)(smc+OFF_H1HI+(size_t)(m0*SP+n0)*2)=hi;
          *(uint32_t*)(smc+OFF_H1LO+(size_t)(m0*SP+n0)*2)=lo;
          split2(v2,v3,hi,lo);
          *(uint32_t*)(smc+OFF_H1HI+(size_t)(m1*SP+n0)*2)=hi;
          *(uint32_t*)(smc+OFF_H1LO+(size_t)(m1*SP+n0)*2)=lo;
        }
      }
    }
    __syncthreads();

    // ---- phase 3: layer-2 MMA + in-register node reduction -> sg2 ----
    {
      float acc[4][2][2];
      #pragma unroll
      for(int nd=0;nd<4;nd++)
        #pragma unroll
        for(int nt=0;nt<2;nt++){acc[nd][nt][0]=0.f;acc[nd][nt][1]=0.f;}
      uint32_t a_off=(uint32_t)(((lane&15)*SP+((lane>>4)<<3))*2);
      for(int Mt=0;Mt<8;Mt++){
        float c[2][4]={{0,0,0,0},{0,0,0,0}};
        uint32_t abase=a_off+(uint32_t)(Mt*16*SP*2);
        #pragma unroll
        for(int ks=0;ks<8;ks++){
          uint32_t ah[4],al[4];
          LDM4(ah, sbase+OFF_H1HI+abase+ks*32);
          LDM4(al, sbase+OFF_H1LO+abase+ks*32);
          #pragma unroll
          for(int nt=0;nt<2;nt++){
            MMA4(c[nt],ah,w2hi[nt][ks][0],w2hi[nt][ks][1]);
            MMA4(c[nt],ah,w2lo[nt][ks][0],w2lo[nt][ks][1]);
            MMA4(c[nt],al,w2hi[nt][ks][0],w2hi[nt][ks][1]);
          }
        }
        int m0=Mt*16+(lane>>2), m1=m0+8;
        int node=Mt>>1;
        bool k0=(m0&31)<KK, k1=(m1&31)<KK;
        #pragma unroll
        for(int nt=0;nt<2;nt++){
          float v0=k0?gelu(c[nt][0]+b2v[nt][0]):0.f;
          float v1=k0?gelu(c[nt][1]+b2v[nt][1]):0.f;
          float v2=k1?gelu(c[nt][2]+b2v[nt][0]):0.f;
          float v3=k1?gelu(c[nt][3]+b2v[nt][1]):0.f;
          acc[node][nt][0]+=v0+v2;
          acc[node][nt][1]+=v1+v3;
        }
      }
      #pragma unroll
      for(int nd=0;nd<4;nd++)
        #pragma unroll
        for(int nt=0;nt<2;nt++)
          #pragma unroll
          for(int cp=0;cp<2;cp++){
            float v=acc[nd][nt][cp];
            v+=__shfl_xor_sync(0xffffffffu,v,4);
            v+=__shfl_xor_sync(0xffffffffu,v,8);
            v+=__shfl_xor_sync(0xffffffffu,v,16);
            acc[nd][nt][cp]=v;
          }
      if(lane<4){
        #pragma unroll
        for(int nd=0;nd<4;nd++)
          #pragma unroll
          for(int nt=0;nt<2;nt++){
            sg2[nd*128+wbase+nt*8+lane*2  ]=acc[nd][nt][0];
            sg2[nd*128+wbase+nt*8+lane*2+1]=acc[nd][nt][1];
          }
      }
    }
    __syncthreads();

    // ---- phase 4: msg = g2@W3, K-split across 2 halves ----
    {
      int j=t&127, kh=t>>7;
      const float* wp=W3w+(size_t)(kh*64)*128+j;
      float a0=0.f,a1=0.f,a2=0.f,a3=0.f;
      int ib=kh*64;
      #pragma unroll 4
      for(int i=0;i<64;i++){
        float wv=wp[(size_t)i*128];
        int ii=ib+i;
        a0+=sg2[0*128+ii]*wv; a1+=sg2[1*128+ii]*wv;
        a2+=sg2[2*128+ii]*wv; a3+=sg2[3*128+ii]*wv;
      }
      float* sp=spart+kh*512;
      sp[0*128+j]=a0; sp[1*128+j]=a1; sp[2*128+j]=a2; sp[3*128+j]=a3;
    }
    __syncthreads();
    {
      #pragma unroll
      for(int o=0;o<2;o++){
        int oo=t+o*256; int nd=oo>>7, j=oo&127;
        float m=(spart[nd*128+j]+spart[512+nd*128+j])*(1.f/(float)KK)+W3b[j];
        sy[nd*132+j]=g_hV[(size_t)(node_base+nd)*128+j]+m;
      }
    }
    __syncthreads();

    // ---- phase 5: LN1 (warp per node) -> g_hV1 ----
    if(w<4){
      float4 v=*(const float4*)&sy[w*132+lane*4];
      float s=v.x+v.y+v.z+v.w;
      #pragma unroll
      for(int o=16;o;o>>=1) s+=__shfl_xor_sync(0xffffffffu,s,o);
      float m=s*(1.f/128.f);
      float dx=v.x-m,dy=v.y-m,dz=v.z-m,dw=v.w-m;
      float q=dx*dx+dy*dy+dz*dz+dw*dw;
      #pragma unroll
      for(int o=16;o;o>>=1) q+=__shfl_xor_sync(0xffffffffu,q,o);
      float rs=rsqrtf(q*(1.f/128.f)+1e-5f);
      float4 gg=*(const float4*)&l1g[lane*4];
      float4 bb=*(const float4*)&l1b[lane*4];
      float4 o4;
      o4.x=dx*rs*gg.x+bb.x; o4.y=dy*rs*gg.y+bb.y;
      o4.z=dz*rs*gg.z+bb.z; o4.w=dw*rs*gg.w+bb.w;
      *(float4*)&g_hV1[(size_t)(node_base+w)*128+lane*4]=o4;
    }
    __syncthreads();
  }
}

// ---------------- kernel 3: HMMA FF + LN2, M=32/block, 2 CTA/SM ----------------
#define FF2_AHI 0
#define FF2_ALO 8704
#define FF2_HHI 17408
#define FF2_HLO 26112
#define FF2_Y   34816
#define FF2_SMEM 51712

__global__ __launch_bounds__(256,2) void k_ff2(
    const float* __restrict__ Wi,const float* __restrict__ bi,
    const float* __restrict__ Wo,const float* __restrict__ bo,
    const float* __restrict__ l2g,const float* __restrict__ l2b,
    float* __restrict__ out){
  extern __shared__ __align__(16) char smc[];
  uint32_t sbase=smem_u32(smc);
  float* sy=(float*)(smc+FF2_Y);
  int t=threadIdx.x, w=t>>5, lane=t&31;
  int base=blockIdx.x*32;

  for(int idx=t; idx<2048; idx+=256){
    int row=idx>>6, cp=idx&63;
    float2 v=*(const float2*)&g_hV1[(size_t)(base+row)*128+cp*2];
    uint32_t hi,lo; split2(v.x,v.y,hi,lo);
    *(uint32_t*)(smc+FF2_AHI+(size_t)(row*SP+cp*2)*2)=hi;
    *(uint32_t*)(smc+FF2_ALO+(size_t)(row*SP+cp*2)*2)=lo;
  }
  __syncthreads();

  float C[2][2][4];
  #pragma unroll
  for(int Mt=0;Mt<2;Mt++)
    #pragma unroll
    for(int nt=0;nt<2;nt++)
      #pragma unroll
      for(int q=0;q<4;q++) C[Mt][nt][q]=0.f;

  uint32_t a_off=(uint32_t)(((lane&15)*SP+((lane>>4)<<3))*2);

  for(int ch=0;ch<4;ch++){
    // ---- GEMM1: load BOTH nt fragment sets, then share A loads ----
    {
      uint32_t fhi[2][8][2], flo[2][8][2];
      #pragma unroll
      for(int nt=0;nt<2;nt++){
        int n=ch*128+w*16+nt*8+(lane>>2);
        #pragma unroll
        for(int ks=0;ks<8;ks++)
          #pragma unroll
          for(int p=0;p<2;p++){
            int k0=ks*16+(lane&3)*2+p*8;
            float wa=Wi[(size_t)k0*512+n], wb=Wi[(size_t)(k0+1)*512+n];
            split2(wa,wb,fhi[nt][ks][p],flo[nt][ks][p]);
          }
      }
      float bi0[2],bi1[2];
      #pragma unroll
      for(int nt=0;nt<2;nt++){
        bi0[nt]=bi[ch*128+w*16+nt*8+(lane&3)*2];
        bi1[nt]=bi[ch*128+w*16+nt*8+(lane&3)*2+1];
      }
      #pragma unroll
      for(int Mt=0;Mt<2;Mt++){
        float c[2][4]={{0,0,0,0},{0,0,0,0}};
        uint32_t abase=a_off+(uint32_t)(Mt*16*SP*2);
        #pragma unroll
        for(int ks=0;ks<8;ks++){
          uint32_t ah[4],al[4];
          LDM4(ah, sbase+FF2_AHI+abase+ks*32);
          LDM4(al, sbase+FF2_ALO+abase+ks*32);
          #pragma unroll
          for(int nt=0;nt<2;nt++){
            MMA4(c[nt],ah,fhi[nt][ks][0],fhi[nt][ks][1]);
            MMA4(c[nt],ah,flo[nt][ks][0],flo[nt][ks][1]);
            MMA4(c[nt],al,fhi[nt][ks][0],fhi[nt][ks][1]);
          }
        }
        int m0=Mt*16+(lane>>2), m1=m0+8;
        #pragma unroll
        for(int nt=0;nt<2;nt++){
          int n0=w*16+nt*8+(lane&3)*2;
          uint32_t hi,lo;
          split2(gelu(c[nt][0]+bi0[nt]),gelu(c[nt][1]+bi1[nt]),hi,lo);
          *(uint32_t*)(smc+FF2_HHI+(size_t)(m0*SP+n0)*2)=hi;
          *(uint32_t*)(smc+FF2_HLO+(size_t)(m0*SP+n0)*2)=lo;
          split2(gelu(c[nt][2]+bi0[nt]),gelu(c[nt][3]+bi1[nt]),hi,lo);
          *(uint32_t*)(smc+FF2_HHI+(size_t)(m1*SP+n0)*2)=hi;
          *(uint32_t*)(smc+FF2_HLO+(size_t)(m1*SP+n0)*2)=lo;
        }
      }
    }
    __syncthreads();

    // ---- GEMM2: load BOTH nt fragment sets, then share A loads ----
    {
      uint32_t fhi[2][8][2], flo[2][8][2];
      #pragma unroll
      for(int nt=0;nt<2;nt++){
        int n=w*16+nt*8+(lane>>2);
        #pragma unroll
        for(int ks=0;ks<8;ks++)
          #pragma unroll
          for(int p=0;p<2;p++){
            int k0=ch*128+ks*16+(lane&3)*2+p*8;
            float wa=Wo[(size_t)k0*128+n], wb=Wo[(size_t)(k0+1)*128+n];
            split2(wa,wb,fhi[nt][ks][p],flo[nt][ks][p]);
          }
      }
      #pragma unroll
      for(int Mt=0;Mt<2;Mt++){
        uint32_t abase=a_off+(uint32_t)(Mt*16*SP*2);
        #pragma unroll
        for(int ks=0;ks<8;ks++){
          uint32_t ah[4],al[4];
          LDM4(ah, sbase+FF2_HHI+abase+ks*32);
          LDM4(al, sbase+FF2_HLO+abase+ks*32);
          #pragma unroll
          for(int nt=0;nt<2;nt++){
            MMA4(C[Mt][nt],ah,fhi[nt][ks][0],fhi[nt][ks][1]);
            MMA4(C[Mt][nt],ah,flo[nt][ks][0],flo[nt][ks][1]);
            MMA4(C[Mt][nt],al,fhi[nt][ks][0],fhi[nt][ks][1]);
          }
        }
      }
    }
    __syncthreads();
  }

  {
    #pragma unroll
    for(int Mt=0;Mt<2;Mt++){
      int m0=Mt*16+(lane>>2), m1=m0+8;
      #pragma unroll
      for(int nt=0;nt<2;nt++){
        int n0=w*16+nt*8+(lane&3)*2;
        float b0=bo[n0], b1=bo[n0+1];
        sy[m0*132+n0  ]=C[Mt][nt][0]+b0+g_hV1[(size_t)(base+m0)*128+n0];
        sy[m0*132+n0+1]=C[Mt][nt][1]+b1+g_hV1[(size_t)(base+m0)*128+n0+1];
        sy[m1*132+n0  ]=C[Mt][nt][2]+b0+g_hV1[(size_t)(base+m1)*128+n0];
        sy[m1*132+n0+1]=C[Mt][nt][3]+b1+g_hV1[(size_t)(base+m1)*128+n0+1];
      }
    }
  }
  __syncthreads();
  for(int r=0;r<4;r++){
    int row=w*4+r;
    float4 v=*(const float4*)&sy[row*132+lane*4];
    float s=v.x+v.y+v.z+v.w;
    #pragma unroll
    for(int o=16;o;o>>=1) s+=__shfl_xor_sync(0xffffffffu,s,o);
    float m=s*(1.f/128.f);
    float dx=v.x-m,dy=v.y-m,dz=v.z-m,dw=v.w-m;
    float q=dx*dx+dy*dy+dz*dz+dw*dw;
    #pragma unroll
    for(int o=16;o;o>>=1) q+=__shfl_xor_sync(0xffffffffu,q,o);
    float rs=rsqrtf(q*(1.f/128.f)+1e-5f);
    float4 gg=*(const float4*)&l2g[lane*4];
    float4 bb=*(const float4*)&l2b[lane*4];
    float4 o4;
    o4.x=dx*rs*gg.x+bb.x; o4.y=dy*rs*gg.y+bb.y;
    o4.z=dz*rs*gg.z+bb.z; o4.w=dw*rs*gg.w+bb.w;
    *(float4*)&out[(size_t)(base+row)*128+lane*4]=o4;
  }
}

// ---------------- launch ----------------
extern "C" void kernel_launch(void* const* d_in, const int* in_sizes, int n_in,
                              void* d_out, int out_size){
  const float* X  =(const float*)d_in[0];
  const int*  Eidx=(const int*  )d_in[1];
  const float* Wvw=(const float*)d_in[2];
  const float* Wvb=(const float*)d_in[3];
  const float* Wew=(const float*)d_in[4];
  const float* Web=(const float*)d_in[5];
  const float* W1w=(const float*)d_in[6];
  const float* W1b=(const float*)d_in[7];
  const float* W2w=(const float*)d_in[8];
  const float* W2b=(const float*)d_in[9];
  const float* W3w=(const float*)d_in[10];
  const float* W3b=(const float*)d_in[11];
  const float* Wiw=(const float*)d_in[12];
  const float* Wib=(const float*)d_in[13];
  const float* Wow=(const float*)d_in[14];
  const float* Wob=(const float*)d_in[15];
  const float* l1g=(const float*)d_in[16];
  const float* l1b=(const float*)d_in[17];
  const float* l2g=(const float*)d_in[18];
  const float* l2b=(const float*)d_in[19];
  float* out=(float*)d_out;

  cudaFuncSetAttribute(k_edge, cudaFuncAttributeMaxDynamicSharedMemorySize,
                       EDGE_SMEM_BYTES);
  cudaFuncSetAttribute(k_ff2, cudaFuncAttributeMaxDynamicSharedMemorySize,
                       FF2_SMEM);

  k_fold<<<17,128>>>(Wew,Web,W1w,W1b);
  k_node<<<NNODES/32,256>>>(X,Wvw,Wvb,W1w);
  k_edge<<<296,256,EDGE_SMEM_BYTES>>>(X,Eidx,W2w,W2b,W3w,W3b,l1g,l1b);
  k_ff2<<<NNODES/32,256,FF2_SMEM>>>(Wiw,Wib,Wow,Wob,l2g,l2b,out);
}

// round 17
// speedup vs baseline: 1.0915x; 1.0195x over previous
#include <cuda_runtime.h>
#include <cuda_bf16.h>
#include <math.h>
#include <stdint.h>

#define BB 4
#define NN 2048
#define KK 30
#define HH 128
#define NNODES (BB*NN)
#define NTILES (NNODES/4)
#define SP 136          // padded bf16 row stride for 128-col MMA activation buffers

// ---------------- device scratch ----------------
__device__ __align__(16) float g_hV  [NNODES*HH];
__device__ __align__(16) float g_Apre[NNODES*HH];
__device__ __align__(16) float g_Cpre[NNODES*HH];
__device__ __align__(16) float g_Q   [NNODES*9];
__device__ __align__(16) float g_hV1 [NNODES*HH];
__device__ __align__(16) float g_Wef [16*HH];
__device__ __align__(16) float g_bef [HH];

// ---------------- geometry helpers ----------------
struct F3{float x,y,z;};
__device__ __forceinline__ F3 f3(float a,float b,float c){F3 r;r.x=a;r.y=b;r.z=c;return r;}
__device__ __forceinline__ F3 sub3(F3 a,F3 b){return f3(a.x-b.x,a.y-b.y,a.z-b.z);}
__device__ __forceinline__ float dot3(F3 a,F3 b){return a.x*b.x+a.y*b.y+a.z*b.z;}
__device__ __forceinline__ F3 cross3(F3 a,F3 b){
  return f3(a.y*b.z-a.z*b.y, a.z*b.x-a.x*b.z, a.x*b.y-a.y*b.x);
}
__device__ __forceinline__ F3 norm3(F3 v){
  float n=dot3(v,v);
  if(n>0.f){float r=rsqrtf(n);return f3(v.x*r,v.y*r,v.z*r);}
  return f3(0.f,0.f,0.f);
}
__device__ __forceinline__ float sgnf(float x){return (x>0.f)?1.f:((x<0.f)?-1.f:0.f);}
__device__ __forceinline__ float gelu(float x){return 0.5f*x*(1.f+erff(x*0.7071067811865475f));}
__device__ __forceinline__ float clip1(float x){return fminf(fmaxf(x,-1.f+1e-7f),1.f-1e-7f);}
__device__ __forceinline__ F3 loadXf(const float* X,int b,int f){
  const float* p=X+(((b*NN)+(f/3))*4+(f%3))*3;
  return f3(p[0],p[1],p[2]);
}

// ---------------- mma helpers ----------------
__device__ __forceinline__ uint32_t smem_u32(const void* p){
  uint32_t a;
  asm("{ .reg .u64 t; cvta.to.shared.u64 t, %1; cvt.u32.u64 %0, t; }":"=r"(a):"l"(p));
  return a;
}
// single-instruction packed f32x2 -> bf16x2 (low = a, high = b), rn rounding
__device__ __forceinline__ uint32_t pkbf(float a,float b){
  uint32_t r;
  asm("cvt.rn.bf16x2.f32 %0, %1, %2;" : "=r"(r) : "f"(b), "f"(a));
  return r;
}
// 6-instruction hi/lo split: hi = pack(bf(a),bf(b)); lo = pack(a-hi.a, b-hi.b)
__device__ __forceinline__ void split2(float a,float b,uint32_t&hi,uint32_t&lo){
  uint32_t h=pkbf(a,b);
  float ha=__uint_as_float(h<<16);
  float hb=__uint_as_float(h&0xffff0000u);
  lo=pkbf(a-ha,b-hb);
  hi=h;
}

#define LDM4(r,addr) \
  asm volatile("ldmatrix.sync.aligned.m8n8.x4.shared.b16 {%0,%1,%2,%3},[%4];" \
    : "=r"((r)[0]),"=r"((r)[1]),"=r"((r)[2]),"=r"((r)[3]) : "r"(addr))

#define MMA4(c,a,b0,b1) \
  asm volatile("mma.sync.aligned.m16n8k16.row.col.f32.bf16.bf16.f32 " \
    "{%0,%1,%2,%3},{%4,%5,%6,%7},{%8,%9},{%0,%1,%2,%3};" \
    : "+f"((c)[0]),"+f"((c)[1]),"+f"((c)[2]),"+f"((c)[3]) \
    : "r"((a)[0]),"r"((a)[1]),"r"((a)[2]),"r"((a)[3]),"r"(b0),"r"(b1))

// ---------------- kernel 0: fold We through W1's hE block ----------------
__global__ void k_fold(const float* __restrict__ Wew,const float* __restrict__ Web,
                       const float* __restrict__ W1w,const float* __restrict__ W1b){
  int j=threadIdx.x; int kb=blockIdx.x;
  if(kb<16){
    float s=0.f;
    for(int m=0;m<128;m++) s+=Wew[kb*128+m]*W1w[(128+m)*128+j];
    g_Wef[kb*128+j]=s;
  }else{
    float s=W1b[j];
    for(int m=0;m<128;m++) s+=Web[m]*W1w[(128+m)*128+j];
    g_bef[j]=s;
  }
}

// ---------------- kernel 1: node geometry + hV + HMMA Apre/Cpre ----------------
__global__ __launch_bounds__(256) void k_node(
    const float* __restrict__ X,const float* __restrict__ Wvw,
    const float* __restrict__ Wvb,const float* __restrict__ W1w){
  __shared__ float sfeat[32][21];
  __shared__ float sQ[32][9];
  __shared__ float shv[32][128];
  __shared__ __align__(16) char shvhi[32*SP*2];
  __shared__ __align__(16) char shvlo[32*SP*2];
  int t=threadIdx.x, w=t>>5, lane=t&31;
  int base=blockIdx.x*32;

  if(t<96){
    int nl=t/3, c=t-nl*3; int g=base+nl; int b=g>>11, n=g&(NN-1);
    int tt=3*n+c-1;
    float cD=1.f,sD=0.f,cA=1.f,sA=0.f;
    if(tt>=0 && tt<=3*NN-4){
      F3 x0=loadXf(X,b,tt),x1=loadXf(X,b,tt+1),x2=loadXf(X,b,tt+2),x3=loadXf(X,b,tt+3);
      F3 u0=norm3(sub3(x1,x0)),u1=norm3(sub3(x2,x1)),u2=norm3(sub3(x3,x2));
      F3 n0=norm3(cross3(u0,u1)),n1=norm3(cross3(u1,u2));
      float cd=clip1(dot3(n0,n1));
      F3 v=norm3(cross3(n0,n1));
      float sg=sgnf(-dot3(v,u1));
      cD=(sg==0.f)?1.f:cd;
      sD=sg*sqrtf(fmaxf(0.f,1.f-cd*cd));
      float ca=clip1(dot3(u0,u1));
      cA=ca; sA=sqrtf(fmaxf(0.f,1.f-ca*ca));
    }
    sfeat[nl][c]=cD; sfeat[nl][3+c]=sD; sfeat[nl][6+c]=cA; sfeat[nl][9+c]=sA;
  }else if(t<128){
    int nl=t-96; int g=base+nl; int b=g>>11, n=g&(NN-1);
    float Qr[9];
    if(n==NN-1){
      #pragma unroll
      for(int k2=0;k2<9;k2++)Qr[k2]=0.f;
    }else{
      F3 x0=loadXf(X,b,3*n),x1=loadXf(X,b,3*n+1),x2=loadXf(X,b,3*n+2);
      F3 u0=norm3(sub3(x1,x0)),u1=norm3(sub3(x2,x1));
      F3 n0=norm3(cross3(u0,u1)),b1=norm3(sub3(u0,u1));
      F3 r2=cross3(b1,n0);
      Qr[0]=b1.x;Qr[1]=b1.y;Qr[2]=b1.z;
      Qr[3]=n0.x;Qr[4]=n0.y;Qr[5]=n0.z;
      Qr[6]=r2.x;Qr[7]=r2.y;Qr[8]=r2.z;
    }
    #pragma unroll
    for(int k2=0;k2<9;k2++){sQ[nl][k2]=Qr[k2];g_Q[g*9+k2]=Qr[k2];}
  }
  __syncthreads();
  if(t<96){
    int nl=t/3, a=t-nl*3; int g=base+nl; int b=g>>11, n=g&(NN-1);
    int atom=(a==0)?0:(a+1);
    const float* Xp=X+((b*NN+n)*4)*3;
    F3 d=f3(Xp[atom*3]-Xp[0],Xp[atom*3+1]-Xp[1],Xp[atom*3+2]-Xp[2]);
    F3 du=f3(sQ[nl][0]*d.x+sQ[nl][1]*d.y+sQ[nl][2]*d.z,
             sQ[nl][3]*d.x+sQ[nl][4]*d.y+sQ[nl][5]*d.z,
             sQ[nl][6]*d.x+sQ[nl][7]*d.y+sQ[nl][8]*d.z);
    du=norm3(du);
    sfeat[nl][12+a*3+0]=du.x; sfeat[nl][12+a*3+1]=du.y; sfeat[nl][12+a*3+2]=du.z;
  }
  __syncthreads();
  {
    int j=t&127, half=t>>7;
    float wv[21];
    #pragma unroll
    for(int i=0;i<21;i++) wv[i]=Wvw[i*128+j];
    float bv=Wvb[j];
    for(int r=0;r<16;r++){
      int nl=half*16+r;
      float a=bv;
      #pragma unroll
      for(int i=0;i<21;i++) a+=sfeat[nl][i]*wv[i];
      shv[nl][j]=a;
      g_hV[(size_t)(base+nl)*128+j]=a;
    }
  }
  __syncthreads();
  for(int idx=t; idx<2048; idx+=256){
    int row=idx>>6, cp=idx&63;
    float a=shv[row][cp*2], bq=shv[row][cp*2+1];
    uint32_t hi,lo; split2(a,bq,hi,lo);
    *(uint32_t*)(shvhi+(size_t)(row*SP+cp*2)*2)=hi;
    *(uint32_t*)(shvlo+(size_t)(row*SP+cp*2)*2)=lo;
  }
  __syncthreads();
  {
    uint32_t hibase=smem_u32(shvhi), lobase=smem_u32(shvlo);
    uint32_t a_off=(uint32_t)(((lane&15)*SP+((lane>>4)<<3))*2);
    bool isA=(w<4);
    #pragma unroll
    for(int nt2=0;nt2<4;nt2++){
      int n0=w*32+nt2*8;
      int col=n0+(lane>>2);
      int ccol=isA?col:(col-128);
      int rbase=isA?0:256;
      uint32_t fhi[8][2], flo[8][2];
      #pragma unroll
      for(int ks=0;ks<8;ks++)
        #pragma unroll
        for(int p=0;p<2;p++){
          int k0=ks*16+(lane&3)*2+p*8;
          float wa=W1w[(size_t)(rbase+k0)*128+ccol];
          float wb=W1w[(size_t)(rbase+k0+1)*128+ccol];
          split2(wa,wb,fhi[ks][p],flo[ks][p]);
        }
      #pragma unroll
      for(int Mt=0;Mt<2;Mt++){
        float c[4]={0,0,0,0};
        uint32_t abase=a_off+(uint32_t)(Mt*16*SP*2);
        #pragma unroll
        for(int ks=0;ks<8;ks++){
          uint32_t ah[4],al[4];
          LDM4(ah, hibase+abase+ks*32);
          LDM4(al, lobase+abase+ks*32);
          MMA4(c,ah,fhi[ks][0],fhi[ks][1]);
          MMA4(c,ah,flo[ks][0],flo[ks][1]);
          MMA4(c,al,fhi[ks][0],fhi[ks][1]);
        }
        int m0=Mt*16+(lane>>2), m1=m0+8;
        int cc0=(isA?n0:(n0-128))+(lane&3)*2;
        float* dst=isA?g_Apre:g_Cpre;
        float2 p0; p0.x=c[0]; p0.y=c[1];
        float2 p1; p1.x=c[2]; p1.y=c[3];
        *(float2*)&dst[(size_t)(base+m0)*128+cc0]=p0;
        *(float2*)&dst[(size_t)(base+m1)*128+cc0]=p1;
      }
    }
  }
}

// ---------------- kernel 2: full-HMMA edge MLP + msg + LN1 ----------------
#define OFF_H1HI  0
#define OFF_H1LO  34816
#define OFF_E16HI 69632
#define OFF_E16LO 75776
#define OFF_APB   81920
#define OFF_NBR   83968
#define OFF_SG2   84480
#define OFF_SY    86528
#define OFF_SPART 88640
#define EDGE_SMEM_BYTES 92736

__global__ __launch_bounds__(256,2) void k_edge(
    const float* __restrict__ X,const int* __restrict__ Eidx,
    const float* __restrict__ W2w,const float* __restrict__ W2b,
    const float* __restrict__ W3w,const float* __restrict__ W3b,
    const float* __restrict__ l1g,const float* __restrict__ l1b){
  extern __shared__ __align__(16) char smc[];
  uint32_t sbase=smem_u32(smc);
  float* sApb=(float*)(smc+OFF_APB);
  int*   snbr=(int*)(smc+OFF_NBR);
  float* sg2 =(float*)(smc+OFF_SG2);
  float* sy  =(float*)(smc+OFF_SY);
  float* spart=(float*)(smc+OFF_SPART);
  int t=threadIdx.x, w=t>>5, lane=t&31;
  int wbase=w*16;

  uint32_t w2hi[2][8][2], w2lo[2][8][2];
  {
    int n=wbase+(lane>>2);
    #pragma unroll
    for(int nt=0;nt<2;nt++)
      #pragma unroll
      for(int ks=0;ks<8;ks++)
        #pragma unroll
        for(int p=0;p<2;p++){
          int k0=ks*16+(lane&3)*2+p*8;
          float wa=W2w[k0*128+n+nt*8], wb=W2w[(k0+1)*128+n+nt*8];
          split2(wa,wb,w2hi[nt][ks][p],w2lo[nt][ks][p]);
        }
  }
  float b2v[2][2];
  #pragma unroll
  for(int nt=0;nt<2;nt++){
    b2v[nt][0]=W2b[wbase+nt*8+(lane&3)*2];
    b2v[nt][1]=W2b[wbase+nt*8+(lane&3)*2+1];
  }

  for(int tile=blockIdx.x; tile<NTILES; tile+=gridDim.x){
    int node_base=tile*4;
    int b=node_base>>11;

    // ---- phase 1: edge geometry -> e16 bf16 hi/lo ; Apre staging ----
    if(t<128){
      int nl=t>>5, slot=t&31; int g=node_base+nl; int n=g&(NN-1);
      int nbr=(slot<KK)?Eidx[g*KK+slot]:0;
      snbr[t]=nbr;
      char* ehi=smc+OFF_E16HI+(size_t)t*48;
      char* elo=smc+OFF_E16LO+(size_t)t*48;
      if(slot<KK){
        float out[16];
        const float* Qo=g_Q+g*9;
        F3 q0=f3(Qo[0],Qo[1],Qo[2]),q1=f3(Qo[3],Qo[4],Qo[5]),q2=f3(Qo[6],Qo[7],Qo[8]);
        const float* Xo=X+(size_t)(b*NN+n)*12;
        F3 xa=f3(Xo[0],Xo[1],Xo[2]);
        const float* Xn=X+(size_t)(b*NN+nbr)*12;
        const int ord[4]={1,0,2,3};
        #pragma unroll
        for(int a=0;a<4;a++){
          int atom=ord[a];
          F3 p=f3(Xn[atom*3],Xn[atom*3+1],Xn[atom*3+2]);
          F3 d=sub3(p,xa);
          F3 du=norm3(f3(dot3(q0,d),dot3(q1,d),dot3(q2,d)));
          out[a*3]=du.x; out[a*3+1]=du.y; out[a*3+2]=du.z;
        }
        const float* Qn=g_Q+(size_t)(b*NN+nbr)*9;
        float R00=q0.x*Qn[0]+q1.x*Qn[3]+q2.x*Qn[6];
        float R01=q0.x*Qn[1]+q1.x*Qn[4]+q2.x*Qn[7];
        float R02=q0.x*Qn[2]+q1.x*Qn[5]+q2.x*Qn[8];
        float R10=q0.y*Qn[0]+q1.y*Qn[3]+q2.y*Qn[6];
        float R11=q0.y*Qn[1]+q1.y*Qn[4]+q2.y*Qn[7];
        float R12=q0.y*Qn[2]+q1.y*Qn[5]+q2.y*Qn[8];
        float R20=q0.z*Qn[0]+q1.z*Qn[3]+q2.z*Qn[6];
        float R21=q0.z*Qn[1]+q1.z*Qn[4]+q2.z*Qn[7];
        float R22=q0.z*Qn[2]+q1.z*Qn[5]+q2.z*Qn[8];
        float m0=0.5f*sqrtf(fabsf(1.f+R00-R11-R22));
        float m1=0.5f*sqrtf(fabsf(1.f-R00+R11-R22));
        float m2=0.5f*sqrtf(fabsf(1.f-R00-R11+R22));
        float qx=sgnf(R21-R12)*m0;
        float qy=sgnf(R02-R20)*m1;
        float qz=sgnf(R10-R01)*m2;
        float qw=0.5f*sqrtf(fmaxf(0.f,1.f+R00+R11+R22));
        float nq=qx*qx+qy*qy+qz*qz+qw*qw;
        if(nq>0.f){float r=rsqrtf(nq);qx*=r;qy*=r;qz*=r;qw*=r;}
        else{qx=0.f;qy=0.f;qz=0.f;qw=0.f;}
        out[12]=qx;out[13]=qy;out[14]=qz;out[15]=qw;
        uint4 h0,l0,h1,l1;
        split2(out[0],out[1],h0.x,l0.x);  split2(out[2],out[3],h0.y,l0.y);
        split2(out[4],out[5],h0.z,l0.z);  split2(out[6],out[7],h0.w,l0.w);
        split2(out[8],out[9],h1.x,l1.x);  split2(out[10],out[11],h1.y,l1.y);
        split2(out[12],out[13],h1.z,l1.z);split2(out[14],out[15],h1.w,l1.w);
        *(uint4*)(ehi)=h0;    *(uint4*)(ehi+16)=h1;
        *(uint4*)(elo)=l0;    *(uint4*)(elo+16)=l1;
      }else{
        uint4 z=make_uint4(0,0,0,0);
        *(uint4*)(ehi)=z; *(uint4*)(ehi+16)=z;
        *(uint4*)(elo)=z; *(uint4*)(elo+16)=z;
      }
    }
    {
      int i0=t, i1=t+256;
      sApb[i0]=g_Apre[(size_t)node_base*128+i0]+g_bef[i0&127];
      sApb[i1]=g_Apre[(size_t)node_base*128+i1]+g_bef[i1&127];
    }
    __syncthreads();

    // ---- phase 2: layer-1 MMA (K=16) + Apre/Cpre/gelu -> h1 hi/lo ----
    // Mt loop UNROLLED so ptxas can front-batch the scattered Cpre LDGs
    {
      uint32_t wefhi[2][2], weflo[2][2];
      {
        int n=wbase+(lane>>2);
        #pragma unroll
        for(int nt=0;nt<2;nt++)
          #pragma unroll
          for(int p=0;p<2;p++){
            int k0=(lane&3)*2+p*8;
            float wa=g_Wef[k0*128+n+nt*8], wb=g_Wef[(k0+1)*128+n+nt*8];
            split2(wa,wb,wefhi[nt][p],weflo[nt][p]);
          }
      }
      uint32_t a_off16=(uint32_t)((lane&15)*48+(lane>>4)*16);
      #pragma unroll
      for(int Mt=0;Mt<8;Mt++){
        float c[2][4]={{0,0,0,0},{0,0,0,0}};
        uint32_t ah[4],al[4];
        LDM4(ah, sbase+OFF_E16HI+a_off16+(uint32_t)(Mt*16*48));
        LDM4(al, sbase+OFF_E16LO+a_off16+(uint32_t)(Mt*16*48));
        #pragma unroll
        for(int nt=0;nt<2;nt++){
          MMA4(c[nt],ah,wefhi[nt][0],wefhi[nt][1]);
          MMA4(c[nt],ah,weflo[nt][0],weflo[nt][1]);
          MMA4(c[nt],al,wefhi[nt][0],wefhi[nt][1]);
        }
        int m0=Mt*16+(lane>>2), m1=m0+8;
        int node=Mt>>1;
        bool k0=(m0&31)<KK, k1=(m1&31)<KK;
        const float* cp0p=g_Cpre+(size_t)(b*NN+snbr[m0])*128;
        const float* cp1p=g_Cpre+(size_t)(b*NN+snbr[m1])*128;
        #pragma unroll
        for(int nt=0;nt<2;nt++){
          int n0=wbase+nt*8+(lane&3)*2;
          float2 ap=*(const float2*)&sApb[node*128+n0];
          float2 cp0=*(const float2*)&cp0p[n0];
          float2 cp1=*(const float2*)&cp1p[n0];
          float v0=k0?gelu(c[nt][0]+ap.x+cp0.x):0.f;
          float v1=k0?gelu(c[nt][1]+ap.y+cp0.y):0.f;
          float v2=k1?gelu(c[nt][2]+ap.x+cp1.x):0.f;
          float v3=k1?gelu(c[nt][3]+ap.y+cp1.y):0.f;
          uint32_t hi,lo;
          split2(v0,v1,hi,lo);
          *(uint32_t*)(smc+OFF_H1HI+(size_t)(m0*SP+n0)*2)=hi;
          *(uint32_t*)(smc+OFF_H1LO+(size_t)(m0*SP+n0)*2)=lo;
          split2(v2,v3,hi,lo);
          *(uint32_t*)(smc+OFF_H1HI+(size_t)(m1*SP+n0)*2)=hi;
          *(uint32_t*)(smc+OFF_H1LO+(size_t)(m1*SP+n0)*2)=lo;
        }
      }
    }
    __syncthreads();

    // ---- phase 3: layer-2 MMA + in-register node reduction -> sg2 ----
    {
      float acc[4][2][2];
      #pragma unroll
      for(int nd=0;nd<4;nd++)
        #pragma unroll
        for(int nt=0;nt<2;nt++){acc[nd][nt][0]=0.f;acc[nd][nt][1]=0.f;}
      uint32_t a_off=(uint32_t)(((lane&15)*SP+((lane>>4)<<3))*2);
      #pragma unroll 2
      for(int Mt=0;Mt<8;Mt++){
        float c[2][4]={{0,0,0,0},{0,0,0,0}};
        uint32_t abase=a_off+(uint32_t)(Mt*16*SP*2);
        #pragma unroll
        for(int ks=0;ks<8;ks++){
          uint32_t ah[4],al[4];
          LDM4(ah, sbase+OFF_H1HI+abase+ks*32);
          LDM4(al, sbase+OFF_H1LO+abase+ks*32);
          #pragma unroll
          for(int nt=0;nt<2;nt++){
            MMA4(c[nt],ah,w2hi[nt][ks][0],w2hi[nt][ks][1]);
            MMA4(c[nt],ah,w2lo[nt][ks][0],w2lo[nt][ks][1]);
            MMA4(c[nt],al,w2hi[nt][ks][0],w2hi[nt][ks][1]);
          }
        }
        int m0=Mt*16+(lane>>2), m1=m0+8;
        int node=Mt>>1;
        bool k0=(m0&31)<KK, k1=(m1&31)<KK;
        #pragma unroll
        for(int nt=0;nt<2;nt++){
          float v0=k0?gelu(c[nt][0]+b2v[nt][0]):0.f;
          float v1=k0?gelu(c[nt][1]+b2v[nt][1]):0.f;
          float v2=k1?gelu(c[nt][2]+b2v[nt][0]):0.f;
          float v3=k1?gelu(c[nt][3]+b2v[nt][1]):0.f;
          acc[node][nt][0]+=v0+v2;
          acc[node][nt][1]+=v1+v3;
        }
      }
      #pragma unroll
      for(int nd=0;nd<4;nd++)
        #pragma unroll
        for(int nt=0;nt<2;nt++)
          #pragma unroll
          for(int cp=0;cp<2;cp++){
            float v=acc[nd][nt][cp];
            v+=__shfl_xor_sync(0xffffffffu,v,4);
            v+=__shfl_xor_sync(0xffffffffu,v,8);
            v+=__shfl_xor_sync(0xffffffffu,v,16);
            acc[nd][nt][cp]=v;
          }
      if(lane<4){
        #pragma unroll
        for(int nd=0;nd<4;nd++)
          #pragma unroll
          for(int nt=0;nt<2;nt++){
            sg2[nd*128+wbase+nt*8+lane*2  ]=acc[nd][nt][0];
            sg2[nd*128+wbase+nt*8+lane*2+1]=acc[nd][nt][1];
          }
      }
    }
    __syncthreads();

    // ---- phase 4: msg = g2@W3, K-split across 2 halves ----
    {
      int j=t&127, kh=t>>7;
      const float* wp=W3w+(size_t)(kh*64)*128+j;
      float a0=0.f,a1=0.f,a2=0.f,a3=0.f;
      int ib=kh*64;
      #pragma unroll 8
      for(int i=0;i<64;i++){
        float wv=wp[(size_t)i*128];
        int ii=ib+i;
        a0+=sg2[0*128+ii]*wv; a1+=sg2[1*128+ii]*wv;
        a2+=sg2[2*128+ii]*wv; a3+=sg2[3*128+ii]*wv;
      }
      float* sp=spart+kh*512;
      sp[0*128+j]=a0; sp[1*128+j]=a1; sp[2*128+j]=a2; sp[3*128+j]=a3;
    }
    __syncthreads();
    {
      #pragma unroll
      for(int o=0;o<2;o++){
        int oo=t+o*256; int nd=oo>>7, j=oo&127;
        float m=(spart[nd*128+j]+spart[512+nd*128+j])*(1.f/(float)KK)+W3b[j];
        sy[nd*132+j]=g_hV[(size_t)(node_base+nd)*128+j]+m;
      }
    }
    __syncthreads();

    // ---- phase 5: LN1 (warp per node) -> g_hV1 ----
    if(w<4){
      float4 v=*(const float4*)&sy[w*132+lane*4];
      float s=v.x+v.y+v.z+v.w;
      #pragma unroll
      for(int o=16;o;o>>=1) s+=__shfl_xor_sync(0xffffffffu,s,o);
      float m=s*(1.f/128.f);
      float dx=v.x-m,dy=v.y-m,dz=v.z-m,dw=v.w-m;
      float q=dx*dx+dy*dy+dz*dz+dw*dw;
      #pragma unroll
      for(int o=16;o;o>>=1) q+=__shfl_xor_sync(0xffffffffu,q,o);
      float rs=rsqrtf(q*(1.f/128.f)+1e-5f);
      float4 gg=*(const float4*)&l1g[lane*4];
      float4 bb=*(const float4*)&l1b[lane*4];
      float4 o4;
      o4.x=dx*rs*gg.x+bb.x; o4.y=dy*rs*gg.y+bb.y;
      o4.z=dz*rs*gg.z+bb.z; o4.w=dw*rs*gg.w+bb.w;
      *(float4*)&g_hV1[(size_t)(node_base+w)*128+lane*4]=o4;
    }
    __syncthreads();
  }
}

// ---------------- kernel 3: HMMA FF + LN2, M=32/block, 2 CTA/SM ----------------
#define FF2_AHI 0
#define FF2_ALO 8704
#define FF2_HHI 17408
#define FF2_HLO 26112
#define FF2_Y   34816
#define FF2_SMEM 51712

__global__ __launch_bounds__(256,2) void k_ff2(
    const float* __restrict__ Wi,const float* __restrict__ bi,
    const float* __restrict__ Wo,const float* __restrict__ bo,
    const float* __restrict__ l2g,const float* __restrict__ l2b,
    float* __restrict__ out){
  extern __shared__ __align__(16) char smc[];
  uint32_t sbase=smem_u32(smc);
  float* sy=(float*)(smc+FF2_Y);
  int t=threadIdx.x, w=t>>5, lane=t&31;
  int base=blockIdx.x*32;

  for(int idx=t; idx<2048; idx+=256){
    int row=idx>>6, cp=idx&63;
    float2 v=*(const float2*)&g_hV1[(size_t)(base+row)*128+cp*2];
    uint32_t hi,lo; split2(v.x,v.y,hi,lo);
    *(uint32_t*)(smc+FF2_AHI+(size_t)(row*SP+cp*2)*2)=hi;
    *(uint32_t*)(smc+FF2_ALO+(size_t)(row*SP+cp*2)*2)=lo;
  }
  __syncthreads();

  float C[2][2][4];
  #pragma unroll
  for(int Mt=0;Mt<2;Mt++)
    #pragma unroll
    for(int nt=0;nt<2;nt++)
      #pragma unroll
      for(int q=0;q<4;q++) C[Mt][nt][q]=0.f;

  uint32_t a_off=(uint32_t)(((lane&15)*SP+((lane>>4)<<3))*2);

  for(int ch=0;ch<4;ch++){
    // ---- GEMM1: load BOTH nt fragment sets, then share A loads ----
    {
      uint32_t fhi[2][8][2], flo[2][8][2];
      #pragma unroll
      for(int nt=0;nt<2;nt++){
        int n=ch*128+w*16+nt*8+(lane>>2);
        #pragma unroll
        for(int ks=0;ks<8;ks++)
          #pragma unroll
          for(int p=0;p<2;p++){
            int k0=ks*16+(lane&3)*2+p*8;
            float wa=Wi[(size_t)k0*512+n], wb=Wi[(size_t)(k0+1)*512+n];
            split2(wa,wb,fhi[nt][ks][p],flo[nt][ks][p]);
          }
      }
      float bi0[2],bi1[2];
      #pragma unroll
      for(int nt=0;nt<2;nt++){
        bi0[nt]=bi[ch*128+w*16+nt*8+(lane&3)*2];
        bi1[nt]=bi[ch*128+w*16+nt*8+(lane&3)*2+1];
      }
      #pragma unroll
      for(int Mt=0;Mt<2;Mt++){
        float c[2][4]={{0,0,0,0},{0,0,0,0}};
        uint32_t abase=a_off+(uint32_t)(Mt*16*SP*2);
        #pragma unroll
        for(int ks=0;ks<8;ks++){
          uint32_t ah[4],al[4];
          LDM4(ah, sbase+FF2_AHI+abase+ks*32);
          LDM4(al, sbase+FF2_ALO+abase+ks*32);
          #pragma unroll
          for(int nt=0;nt<2;nt++){
            MMA4(c[nt],ah,fhi[nt][ks][0],fhi[nt][ks][1]);
            MMA4(c[nt],ah,flo[nt][ks][0],flo[nt][ks][1]);
            MMA4(c[nt],al,fhi[nt][ks][0],fhi[nt][ks][1]);
          }
        }
        int m0=Mt*16+(lane>>2), m1=m0+8;
        #pragma unroll
        for(int nt=0;nt<2;nt++){
          int n0=w*16+nt*8+(lane&3)*2;
          uint32_t hi,lo;
          split2(gelu(c[nt][0]+bi0[nt]),gelu(c[nt][1]+bi1[nt]),hi,lo);
          *(uint32_t*)(smc+FF2_HHI+(size_t)(m0*SP+n0)*2)=hi;
          *(uint32_t*)(smc+FF2_HLO+(size_t)(m0*SP+n0)*2)=lo;
          split2(gelu(c[nt][2]+bi0[nt]),gelu(c[nt][3]+bi1[nt]),hi,lo);
          *(uint32_t*)(smc+FF2_HHI+(size_t)(m1*SP+n0)*2)=hi;
          *(uint32_t*)(smc+FF2_HLO+(size_t)(m1*SP+n0)*2)=lo;
        }
      }
    }
    __syncthreads();

    // ---- GEMM2: load BOTH nt fragment sets, then share A loads ----
    {
      uint32_t fhi[2][8][2], flo[2][8][2];
      #pragma unroll
      for(int nt=0;nt<2;nt++){
        int n=w*16+nt*8+(lane>>2);
        #pragma unroll
        for(int ks=0;ks<8;ks++)
          #pragma unroll
          for(int p=0;p<2;p++){
            int k0=ch*128+ks*16+(lane&3)*2+p*8;
            float wa=Wo[(size_t)k0*128+n], wb=Wo[(size_t)(k0+1)*128+n];
            split2(wa,wb,fhi[nt][ks][p],flo[nt][ks][p]);
          }
      }
      #pragma unroll
      for(int Mt=0;Mt<2;Mt++){
        uint32_t abase=a_off+(uint32_t)(Mt*16*SP*2);
        #pragma unroll
        for(int ks=0;ks<8;ks++){
          uint32_t ah[4],al[4];
          LDM4(ah, sbase+FF2_HHI+abase+ks*32);
          LDM4(al, sbase+FF2_HLO+abase+ks*32);
          #pragma unroll
          for(int nt=0;nt<2;nt++){
            MMA4(C[Mt][nt],ah,fhi[nt][ks][0],fhi[nt][ks][1]);
            MMA4(C[Mt][nt],ah,flo[nt][ks][0],flo[nt][ks][1]);
            MMA4(C[Mt][nt],al,fhi[nt][ks][0],fhi[nt][ks][1]);
          }
        }
      }
    }
    __syncthreads();
  }

  {
    #pragma unroll
    for(int Mt=0;Mt<2;Mt++){
      int m0=Mt*16+(lane>>2), m1=m0+8;
      #pragma unroll
      for(int nt=0;nt<2;nt++){
        int n0=w*16+nt*8+(lane&3)*2;
        float b0=bo[n0], b1=bo[n0+1];
        sy[m0*132+n0  ]=C[Mt][nt][0]+b0+g_hV1[(size_t)(base+m0)*128+n0];
        sy[m0*132+n0+1]=C[Mt][nt][1]+b1+g_hV1[(size_t)(base+m0)*128+n0+1];
        sy[m1*132+n0  ]=C[Mt][nt][2]+b0+g_hV1[(size_t)(base+m1)*128+n0];
        sy[m1*132+n0+1]=C[Mt][nt][3]+b1+g_hV1[(size_t)(base+m1)*128+n0+1];
      }
    }
  }
  __syncthreads();
  for(int r=0;r<4;r++){
    int row=w*4+r;
    float4 v=*(const float4*)&sy[row*132+lane*4];
    float s=v.x+v.y+v.z+v.w;
    #pragma unroll
    for(int o=16;o;o>>=1) s+=__shfl_xor_sync(0xffffffffu,s,o);
    float m=s*(1.f/128.f);
    float dx=v.x-m,dy=v.y-m,dz=v.z-m,dw=v.w-m;
    float q=dx*dx+dy*dy+dz*dz+dw*dw;
    #pragma unroll
    for(int o=16;o;o>>=1) q+=__shfl_xor_sync(0xffffffffu,q,o);
    float rs=rsqrtf(q*(1.f/128.f)+1e-5f);
    float4 gg=*(const float4*)&l2g[lane*4];
    float4 bb=*(const float4*)&l2b[lane*4];
    float4 o4;
    o4.x=dx*rs*gg.x+bb.x; o4.y=dy*rs*gg.y+bb.y;
    o4.z=dz*rs*gg.z+bb.z; o4.w=dw*rs*gg.w+bb.w;
    *(float4*)&out[(size_t)(base+row)*128+lane*4]=o4;
  }
}

// ---------------- launch ----------------
extern "C" void kernel_launch(void* const* d_in, const int* in_sizes, int n_in,
                              void* d_out, int out_size){
  const float* X  =(const float*)d_in[0];
  const int*  Eidx=(const int*  )d_in[1];
  const float* Wvw=(const float*)d_in[2];
  const float* Wvb=(const float*)d_in[3];
  const float* Wew=(const float*)d_in[4];
  const float* Web=(const float*)d_in[5];
  const float* W1w=(const float*)d_in[6];
  const float* W1b=(const float*)d_in[7];
  const float* W2w=(const float*)d_in[8];
  const float* W2b=(const float*)d_in[9];
  const float* W3w=(const float*)d_in[10];
  const float* W3b=(const float*)d_in[11];
  const float* Wiw=(const float*)d_in[12];
  const float* Wib=(const float*)d_in[13];
  const float* Wow=(const float*)d_in[14];
  const float* Wob=(const float*)d_in[15];
  const float* l1g=(const float*)d_in[16];
  const float* l1b=(const float*)d_in[17];
  const float* l2g=(const float*)d_in[18];
  const float* l2b=(const float*)d_in[19];
  float* out=(float*)d_out;

  cudaFuncSetAttribute(k_edge, cudaFuncAttributeMaxDynamicSharedMemorySize,
                       EDGE_SMEM_BYTES);
  cudaFuncSetAttribute(k_ff2, cudaFuncAttributeMaxDynamicSharedMemorySize,
                       FF2_SMEM);

  k_fold<<<17,128>>>(Wew,Web,W1w,W1b);
  k_node<<<NNODES/32,256>>>(X,Wvw,Wvb,W1w);
  k_edge<<<296,256,EDGE_SMEM_BYTES>>>(X,Eidx,W2w,W2b,W3w,W3b,l1g,l1b);
  k_ff2<<<NNODES/32,256,FF2_SMEM>>>(Wiw,Wib,Wow,Wob,l2g,l2b,out);
}